// round 1
// baseline (speedup 1.0000x reference)
#include <cuda_runtime.h>
#include <math.h>

#define DM    1024
#define BATCH 4
#define SEQ   2048
#define DVAL  64
#define MTOT  (BATCH*SEQ)   // 8192

// Scratch (device globals — no allocations allowed)
__device__ float g_Q[(size_t)MTOT * DM];
__device__ float g_K[(size_t)MTOT * DM];
__device__ float g_V[(size_t)MTOT * DM];
__device__ float g_P[(size_t)BATCH * SEQ * SEQ];   // scores -> probs (in place)
__device__ float g_C[(size_t)MTOT * DM];           // context

#define BM 128
#define BN 64
#define BK 16

__device__ __forceinline__ float neg_inf() { return __int_as_float(0xff800000); }

// C[M,N] = A[M,K] * B, where B is [N,K] if TRANSB (NT) else [K,N] (NN).
// MASK: causal epilogue (keep col<=row, scale kept, -inf masked) + full-tile skip.
// KLIMIT: truncate k-loop at (m0+BM) (rows of A beyond col m0+BM-1 are zero — causal P).
template<bool TRANSB, bool MASK, bool KLIMIT>
__global__ __launch_bounds__(256, 2)
void gemm_kernel(const float* __restrict__ A, const float* __restrict__ Bm,
                 float* __restrict__ C, int K, int lda, int ldb, int ldc,
                 long long zsA, long long zsB, long long zsC, float scale)
{
    __shared__ float As[BK][BM + 4];
    __shared__ float Bs[BK][BN + 4];

    const int tid = threadIdx.x;
    const int tx = tid & 15;      // 0..15 -> 4 cols each
    const int ty = tid >> 4;      // 0..15 -> 8 rows each
    const int m0 = blockIdx.y * BM;
    const int n0 = blockIdx.x * BN;

    A  += (long long)blockIdx.z * zsA;
    Bm += (long long)blockIdx.z * zsB;
    C  += (long long)blockIdx.z * zsC;

    if (MASK && n0 > m0 + (BM - 1)) {
        // fully above the diagonal: write -inf, no compute
        const float ni = neg_inf();
        float4 v = make_float4(ni, ni, ni, ni);
        #pragma unroll
        for (int i = 0; i < 8; i++) {
            int r = m0 + ty * 8 + i;
            *(float4*)(&C[(long long)r * ldc + n0 + tx * 4]) = v;
        }
        return;
    }

    float acc[8][4];
    #pragma unroll
    for (int i = 0; i < 8; i++)
        #pragma unroll
        for (int j = 0; j < 4; j++) acc[i][j] = 0.0f;

    int ktiles = K / BK;
    if (KLIMIT) ktiles = (m0 + BM) / BK;   // divisible by BK for these shapes

    const int arow = tid >> 2;        // 0..63
    const int akv  = (tid & 3) * 4;   // 0,4,8,12

    for (int kt = 0; kt < ktiles; kt++) {
        const int k0 = kt * BK;
        // --- load A tile (128 x 16), transposed into As[k][m] ---
        float4 a0 = *(const float4*)(A + (long long)(m0 + arow)      * lda + k0 + akv);
        float4 a1 = *(const float4*)(A + (long long)(m0 + arow + 64) * lda + k0 + akv);
        As[akv + 0][arow] = a0.x; As[akv + 1][arow] = a0.y;
        As[akv + 2][arow] = a0.z; As[akv + 3][arow] = a0.w;
        As[akv + 0][arow + 64] = a1.x; As[akv + 1][arow + 64] = a1.y;
        As[akv + 2][arow + 64] = a1.z; As[akv + 3][arow + 64] = a1.w;
        // --- load B tile (64 x 16 NT, or 16 x 64 NN) ---
        if (TRANSB) {
            float4 b0 = *(const float4*)(Bm + (long long)(n0 + arow) * ldb + k0 + akv);
            Bs[akv + 0][arow] = b0.x; Bs[akv + 1][arow] = b0.y;
            Bs[akv + 2][arow] = b0.z; Bs[akv + 3][arow] = b0.w;
        } else {
            float4 b0 = *(const float4*)(Bm + (long long)(k0 + ty) * ldb + n0 + tx * 4);
            *(float4*)(&Bs[ty][tx * 4]) = b0;
        }
        __syncthreads();

        #pragma unroll
        for (int kk = 0; kk < BK; kk++) {
            float4 av0 = *(const float4*)(&As[kk][ty * 8]);
            float4 av1 = *(const float4*)(&As[kk][ty * 8 + 4]);
            float4 bv  = *(const float4*)(&Bs[kk][tx * 4]);
            float a[8] = {av0.x, av0.y, av0.z, av0.w, av1.x, av1.y, av1.z, av1.w};
            float b[4] = {bv.x, bv.y, bv.z, bv.w};
            #pragma unroll
            for (int i = 0; i < 8; i++)
                #pragma unroll
                for (int j = 0; j < 4; j++)
                    acc[i][j] = fmaf(a[i], b[j], acc[i][j]);
        }
        __syncthreads();
    }

    const float ni = neg_inf();
    #pragma unroll
    for (int i = 0; i < 8; i++) {
        int r = m0 + ty * 8 + i;
        float4 v = make_float4(acc[i][0], acc[i][1], acc[i][2], acc[i][3]);
        if (MASK) {
            int c0 = n0 + tx * 4;
            v.x = (c0 + 0 <= r) ? v.x * scale : ni;
            v.y = (c0 + 1 <= r) ? v.y * scale : ni;
            v.z = (c0 + 2 <= r) ? v.z * scale : ni;
            v.w = (c0 + 3 <= r) ? v.w * scale : ni;
        }
        *(float4*)(&C[(long long)r * ldc + n0 + tx * 4]) = v;
    }
}

// Row softmax over g_P, one block per row, in place. -inf entries -> 0.
__global__ __launch_bounds__(256)
void softmax_kernel()
{
    const long long row = blockIdx.x;
    float4* p4 = (float4*)(g_P + row * SEQ);
    const int tid = threadIdx.x;
    __shared__ float red[256];

    float m = neg_inf();
    #pragma unroll
    for (int i = tid; i < SEQ / 4; i += 256) {
        float4 v = p4[i];
        m = fmaxf(m, fmaxf(fmaxf(v.x, v.y), fmaxf(v.z, v.w)));
    }
    red[tid] = m; __syncthreads();
    for (int s = 128; s > 0; s >>= 1) {
        if (tid < s) red[tid] = fmaxf(red[tid], red[tid + s]);
        __syncthreads();
    }
    m = red[0];
    __syncthreads();

    float sum = 0.0f;
    #pragma unroll
    for (int i = tid; i < SEQ / 4; i += 256) {
        float4 v = p4[i];
        v.x = __expf(v.x - m); v.y = __expf(v.y - m);
        v.z = __expf(v.z - m); v.w = __expf(v.w - m);
        sum += (v.x + v.y) + (v.z + v.w);
        p4[i] = v;
    }
    red[tid] = sum; __syncthreads();
    for (int s = 128; s > 0; s >>= 1) {
        if (tid < s) red[tid] += red[tid + s];
        __syncthreads();
    }
    const float inv = 1.0f / red[0];
    __syncthreads();

    #pragma unroll
    for (int i = tid; i < SEQ / 4; i += 256) {
        float4 v = p4[i];
        v.x *= inv; v.y *= inv; v.z *= inv; v.w *= inv;
        p4[i] = v;
    }
}

extern "C" void kernel_launch(void* const* d_in, const int* in_sizes, int n_in,
                              void* d_out, int out_size)
{
    const float* x  = (const float*)d_in[0];
    const float* Wq = (const float*)d_in[1];
    const float* Wk = (const float*)d_in[2];
    const float* Wv = (const float*)d_in[3];
    const float* Wo = (const float*)d_in[4];
    float* out = (float*)d_out;

    float *Q, *K, *V, *P, *CTX;
    cudaGetSymbolAddress((void**)&Q,   g_Q);
    cudaGetSymbolAddress((void**)&K,   g_K);
    cudaGetSymbolAddress((void**)&V,   g_V);
    cudaGetSymbolAddress((void**)&P,   g_P);
    cudaGetSymbolAddress((void**)&CTX, g_C);

    const dim3 blk(256);
    const float scale = 1.0f / 32.0f;   // 1/sqrt(1024)

    // 1) Q, K, V projections: [8192,1024] = x @ W^T
    gemm_kernel<true, false, false><<<dim3(DM / BN, MTOT / BM, 1), blk>>>(
        x, Wq, Q, DM, DM, DM, DM, 0, 0, 0, 1.0f);
    gemm_kernel<true, false, false><<<dim3(DM / BN, MTOT / BM, 1), blk>>>(
        x, Wk, K, DM, DM, DM, DM, 0, 0, 0, 1.0f);
    gemm_kernel<true, false, false><<<dim3(DM / BN, MTOT / BM, 1), blk>>>(
        x, Wv, V, DM, DM, DM, DM, 0, 0, 0, 1.0f);

    // 2) scores = mask(Q @ K^T) * scale  per batch  [S,S]
    gemm_kernel<true, true, false><<<dim3(SEQ / BN, SEQ / BM, BATCH), blk>>>(
        Q, K, P, DM, DM, DM, SEQ,
        (long long)SEQ * DM, (long long)SEQ * DM, (long long)SEQ * SEQ, scale);

    // 3) row softmax (in place)
    softmax_kernel<<<BATCH * SEQ, 256>>>();

    // 4) ctx = P @ V  per batch  [S,D], causal k-limit
    gemm_kernel<false, false, true><<<dim3(DM / BN, SEQ / BM, BATCH), blk>>>(
        P, V, CTX, SEQ, SEQ, DM, DM,
        (long long)SEQ * SEQ, (long long)SEQ * DM, (long long)SEQ * DM, 1.0f);

    // 5) out = ctx @ Wo^T  [8192,64]
    gemm_kernel<true, false, false><<<dim3(DVAL / BN, MTOT / BM, 1), blk>>>(
        CTX, Wo, out, DM, DM, DM, DVAL, 0, 0, 0, 1.0f);
}

// round 2
// speedup vs baseline: 1.0033x; 1.0033x over previous
#include <cuda_runtime.h>
#include <math.h>

#define DM    1024
#define BATCH 4
#define SEQ   2048
#define DVAL  64
#define MTOT  (BATCH*SEQ)   // 8192

// Scratch (device globals — no allocations allowed)
__device__ float g_Q[(size_t)MTOT * DM];
__device__ float g_K[(size_t)MTOT * DM];
__device__ float g_V[(size_t)MTOT * DM];
__device__ float g_P[(size_t)BATCH * SEQ * SEQ];   // scores -> probs (in place)
__device__ float g_C[(size_t)MTOT * DM];           // context

#define BM 128
#define BN 64
#define BK 16

__device__ __forceinline__ float neg_inf() { return __int_as_float(0xff800000); }

// C[M,N] = A[M,K] * B, where B is [N,K] if TRANSB (NT) else [K,N] (NN).
// MASK: causal epilogue (keep col<=row, scale kept, -inf masked) + full-tile skip.
// KLIMIT: truncate k-loop at (m0+BM) (rows of A beyond col m0+BM-1 are zero — causal P).
template<bool TRANSB, bool MASK, bool KLIMIT>
__global__ __launch_bounds__(256, 2)
void gemm_kernel(const float* __restrict__ A, const float* __restrict__ Bm,
                 float* __restrict__ C, int K, int lda, int ldb, int ldc,
                 long long zsA, long long zsB, long long zsC, float scale)
{
    __shared__ float As[BK][BM + 4];
    __shared__ float Bs[BK][BN + 4];

    const int tid = threadIdx.x;
    const int tx = tid & 15;      // 0..15 -> 4 cols each
    const int ty = tid >> 4;      // 0..15 -> 8 rows each
    const int m0 = blockIdx.y * BM;
    const int n0 = blockIdx.x * BN;

    A  += (long long)blockIdx.z * zsA;
    Bm += (long long)blockIdx.z * zsB;
    C  += (long long)blockIdx.z * zsC;

    if (MASK && n0 > m0 + (BM - 1)) {
        // fully above the diagonal: write -inf, no compute
        const float ni = neg_inf();
        float4 v = make_float4(ni, ni, ni, ni);
        #pragma unroll
        for (int i = 0; i < 8; i++) {
            int r = m0 + ty * 8 + i;
            *(float4*)(&C[(long long)r * ldc + n0 + tx * 4]) = v;
        }
        return;
    }

    float acc[8][4];
    #pragma unroll
    for (int i = 0; i < 8; i++)
        #pragma unroll
        for (int j = 0; j < 4; j++) acc[i][j] = 0.0f;

    int ktiles = K / BK;
    if (KLIMIT) ktiles = (m0 + BM) / BK;   // divisible by BK for these shapes

    const int arow = tid >> 2;        // 0..63
    const int akv  = (tid & 3) * 4;   // 0,4,8,12

    for (int kt = 0; kt < ktiles; kt++) {
        const int k0 = kt * BK;
        // --- load A tile (128 x 16), transposed into As[k][m] ---
        float4 a0 = *(const float4*)(A + (long long)(m0 + arow)      * lda + k0 + akv);
        float4 a1 = *(const float4*)(A + (long long)(m0 + arow + 64) * lda + k0 + akv);
        As[akv + 0][arow] = a0.x; As[akv + 1][arow] = a0.y;
        As[akv + 2][arow] = a0.z; As[akv + 3][arow] = a0.w;
        As[akv + 0][arow + 64] = a1.x; As[akv + 1][arow + 64] = a1.y;
        As[akv + 2][arow + 64] = a1.z; As[akv + 3][arow + 64] = a1.w;
        // --- load B tile (64 x 16 NT, or 16 x 64 NN) ---
        if (TRANSB) {
            float4 b0 = *(const float4*)(Bm + (long long)(n0 + arow) * ldb + k0 + akv);
            Bs[akv + 0][arow] = b0.x; Bs[akv + 1][arow] = b0.y;
            Bs[akv + 2][arow] = b0.z; Bs[akv + 3][arow] = b0.w;
        } else {
            float4 b0 = *(const float4*)(Bm + (long long)(k0 + ty) * ldb + n0 + tx * 4);
            *(float4*)(&Bs[ty][tx * 4]) = b0;
        }
        __syncthreads();

        #pragma unroll
        for (int kk = 0; kk < BK; kk++) {
            float4 av0 = *(const float4*)(&As[kk][ty * 8]);
            float4 av1 = *(const float4*)(&As[kk][ty * 8 + 4]);
            float4 bv  = *(const float4*)(&Bs[kk][tx * 4]);
            float a[8] = {av0.x, av0.y, av0.z, av0.w, av1.x, av1.y, av1.z, av1.w};
            float b[4] = {bv.x, bv.y, bv.z, bv.w};
            #pragma unroll
            for (int i = 0; i < 8; i++)
                #pragma unroll
                for (int j = 0; j < 4; j++)
                    acc[i][j] = fmaf(a[i], b[j], acc[i][j]);
        }
        __syncthreads();
    }

    const float ni = neg_inf();
    #pragma unroll
    for (int i = 0; i < 8; i++) {
        int r = m0 + ty * 8 + i;
        float4 v = make_float4(acc[i][0], acc[i][1], acc[i][2], acc[i][3]);
        if (MASK) {
            int c0 = n0 + tx * 4;
            v.x = (c0 + 0 <= r) ? v.x * scale : ni;
            v.y = (c0 + 1 <= r) ? v.y * scale : ni;
            v.z = (c0 + 2 <= r) ? v.z * scale : ni;
            v.w = (c0 + 3 <= r) ? v.w * scale : ni;
        }
        *(float4*)(&C[(long long)r * ldc + n0 + tx * 4]) = v;
    }
}

// Row softmax over g_P, one block per row, in place. -inf entries -> 0.
__global__ __launch_bounds__(256)
void softmax_kernel()
{
    const long long row = blockIdx.x;
    float4* p4 = (float4*)(g_P + row * SEQ);
    const int tid = threadIdx.x;
    __shared__ float red[256];

    float m = neg_inf();
    #pragma unroll
    for (int i = tid; i < SEQ / 4; i += 256) {
        float4 v = p4[i];
        m = fmaxf(m, fmaxf(fmaxf(v.x, v.y), fmaxf(v.z, v.w)));
    }
    red[tid] = m; __syncthreads();
    for (int s = 128; s > 0; s >>= 1) {
        if (tid < s) red[tid] = fmaxf(red[tid], red[tid + s]);
        __syncthreads();
    }
    m = red[0];
    __syncthreads();

    float sum = 0.0f;
    #pragma unroll
    for (int i = tid; i < SEQ / 4; i += 256) {
        float4 v = p4[i];
        v.x = __expf(v.x - m); v.y = __expf(v.y - m);
        v.z = __expf(v.z - m); v.w = __expf(v.w - m);
        sum += (v.x + v.y) + (v.z + v.w);
        p4[i] = v;
    }
    red[tid] = sum; __syncthreads();
    for (int s = 128; s > 0; s >>= 1) {
        if (tid < s) red[tid] += red[tid + s];
        __syncthreads();
    }
    const float inv = 1.0f / red[0];
    __syncthreads();

    #pragma unroll
    for (int i = tid; i < SEQ / 4; i += 256) {
        float4 v = p4[i];
        v.x *= inv; v.y *= inv; v.z *= inv; v.w *= inv;
        p4[i] = v;
    }
}

extern "C" void kernel_launch(void* const* d_in, const int* in_sizes, int n_in,
                              void* d_out, int out_size)
{
    const float* x  = (const float*)d_in[0];
    const float* Wq = (const float*)d_in[1];
    const float* Wk = (const float*)d_in[2];
    const float* Wv = (const float*)d_in[3];
    const float* Wo = (const float*)d_in[4];
    float* out = (float*)d_out;

    float *Q, *K, *V, *P, *CTX;
    cudaGetSymbolAddress((void**)&Q,   g_Q);
    cudaGetSymbolAddress((void**)&K,   g_K);
    cudaGetSymbolAddress((void**)&V,   g_V);
    cudaGetSymbolAddress((void**)&P,   g_P);
    cudaGetSymbolAddress((void**)&CTX, g_C);

    const dim3 blk(256);
    const float scale = 1.0f / 32.0f;   // 1/sqrt(1024)

    // 1) Q, K, V projections: [8192,1024] = x @ W^T
    gemm_kernel<true, false, false><<<dim3(DM / BN, MTOT / BM, 1), blk>>>(
        x, Wq, Q, DM, DM, DM, DM, 0, 0, 0, 1.0f);
    gemm_kernel<true, false, false><<<dim3(DM / BN, MTOT / BM, 1), blk>>>(
        x, Wk, K, DM, DM, DM, DM, 0, 0, 0, 1.0f);
    gemm_kernel<true, false, false><<<dim3(DM / BN, MTOT / BM, 1), blk>>>(
        x, Wv, V, DM, DM, DM, DM, 0, 0, 0, 1.0f);

    // 2) scores = mask(Q @ K^T) * scale  per batch  [S,S]
    gemm_kernel<true, true, false><<<dim3(SEQ / BN, SEQ / BM, BATCH), blk>>>(
        Q, K, P, DM, DM, DM, SEQ,
        (long long)SEQ * DM, (long long)SEQ * DM, (long long)SEQ * SEQ, scale);

    // 3) row softmax (in place)
    softmax_kernel<<<BATCH * SEQ, 256>>>();

    // 4) ctx = P @ V  per batch  [S,D], causal k-limit
    gemm_kernel<false, false, true><<<dim3(DM / BN, SEQ / BM, BATCH), blk>>>(
        P, V, CTX, SEQ, SEQ, DM, DM,
        (long long)SEQ * SEQ, (long long)SEQ * DM, (long long)SEQ * DM, 1.0f);

    // 5) out = ctx @ Wo^T  [8192,64]
    gemm_kernel<true, false, false><<<dim3(DVAL / BN, MTOT / BM, 1), blk>>>(
        CTX, Wo, out, DM, DM, DM, DVAL, 0, 0, 0, 1.0f);
}

// round 4
// speedup vs baseline: 2.7767x; 2.7675x over previous
#include <cuda_runtime.h>
#include <cstdint>
#include <math.h>

#define DM    1024
#define BATCH 4
#define SEQ   2048
#define DVAL  64
#define MTOT  (BATCH*SEQ)   // 8192

// Scratch (device globals — no allocations allowed)
__device__ float g_Q[(size_t)MTOT * DM];
__device__ float g_K[(size_t)MTOT * DM];
__device__ float g_V[(size_t)MTOT * DM];
__device__ float g_P[(size_t)BATCH * SEQ * SEQ];
__device__ float g_C[(size_t)MTOT * DM];

// ---------------- helpers ----------------
__device__ __forceinline__ float tf32r(float x) {
    uint32_t r;
    asm("cvt.rna.tf32.f32 %0, %1;" : "=r"(r) : "f"(x));
    return __uint_as_float(r);
}
__device__ __forceinline__ float4 tf32r4(float4 v) {
    v.x = tf32r(v.x); v.y = tf32r(v.y); v.z = tf32r(v.z); v.w = tf32r(v.w);
    return v;
}

// mma.sync m16n8k8 tf32: D += A*B, row.col
__device__ __forceinline__ void mma8(float* c, const float* a, const float* b) {
    asm volatile(
        "mma.sync.aligned.m16n8k8.row.col.f32.tf32.tf32.f32 "
        "{%0,%1,%2,%3}, {%4,%5,%6,%7}, {%8,%9}, {%0,%1,%2,%3};"
        : "+f"(c[0]), "+f"(c[1]), "+f"(c[2]), "+f"(c[3])
        : "r"(__float_as_uint(a[0])), "r"(__float_as_uint(a[1])),
          "r"(__float_as_uint(a[2])), "r"(__float_as_uint(a[3])),
          "r"(__float_as_uint(b[0])), "r"(__float_as_uint(b[1])));
}

// ---------------- tensor-core GEMM ----------------
// C[M,N] = A[M,K] * B.  TRANSB: B is [N,K] (NT).  else B is [K,N] (NN).
// MASK: causal mask + scale epilogue; full-tile skip.
// KLIMIT: truncate K at m0+128 (causal P has exact zeros beyond).
#define TILE_M 128
#define BK     32
#define SA     36              // A (and NT-B) row stride in floats

template<int TILE_N, bool TRANSB, bool MASK, bool KLIMIT>
__global__ __launch_bounds__(256, 1)
void mm_mma(const float* __restrict__ A, const float* __restrict__ Bm,
            float* __restrict__ C, int K, int lda, int ldb, int ldc,
            long long zsA, long long zsB, long long zsC, float scale)
{
    extern __shared__ float sm[];
    constexpr int ASTG = TILE_M * SA;                     // A stage floats
    constexpr int SB   = TRANSB ? SA : (TILE_N + 4);      // B row stride
    constexpr int BSTG = TRANSB ? TILE_N * SA : BK * (TILE_N + 4);
    float* As = sm;                // 2 stages
    float* Bs = sm + 2 * ASTG;     // 2 stages

    const int tid  = threadIdx.x;
    const int lane = tid & 31;
    const int wid  = tid >> 5;
    const int wm   = wid & 1;        // 2 M-slots of 64
    const int wn   = wid >> 1;       // 4 N-slots
    constexpr int WN = TILE_N / 4;   // warp N extent
    constexpr int NF = WN / 8;       // B frags per warp

    const int m0 = blockIdx.y * TILE_M;
    const int n0 = blockIdx.x * TILE_N;

    A  += (long long)blockIdx.z * zsA;
    Bm += (long long)blockIdx.z * zsB;
    C  += (long long)blockIdx.z * zsC;

    if (MASK && n0 > m0 + (TILE_M - 1)) {
        const float ni = __int_as_float(0xff800000);
        float4 v = make_float4(ni, ni, ni, ni);
        for (int i = tid; i < TILE_M * TILE_N / 4; i += 256) {
            int r = i / (TILE_N / 4), c4 = i % (TILE_N / 4);
            *(float4*)&C[(long long)(m0 + r) * ldc + n0 + c4 * 4] = v;
        }
        return;
    }

    float acc[4][NF][4];
    #pragma unroll
    for (int i = 0; i < 4; i++)
        #pragma unroll
        for (int j = 0; j < NF; j++)
            #pragma unroll
            for (int q = 0; q < 4; q++) acc[i][j][q] = 0.0f;

    const int ktiles = KLIMIT ? (m0 + TILE_M) / BK : K / BK;

    constexpr int AIT = TILE_M * 8 / 256;  // 4 float4 per thread
    constexpr int BIT = TRANSB ? TILE_N * 8 / 256 : BK * (TILE_N / 4) / 256;

    float4 pa[AIT], pb[BIT];

    // gmem index precompute
    const int ar  = tid >> 3;        // A row step base (with +32*j? no: i=tid+j*256 -> r=i>>3)
    const int ac4 = tid & 7;

    // ---- prologue: load k-tile 0 ----
    #pragma unroll
    for (int j = 0; j < AIT; j++) {
        int r = (tid + j * 256) >> 3, c4 = (tid + j * 256) & 7;
        pa[j] = *(const float4*)&A[(long long)(m0 + r) * lda + c4 * 4];
    }
    if (TRANSB) {
        #pragma unroll
        for (int j = 0; j < BIT; j++) {
            int r = (tid + j * 256) >> 3, c4 = (tid + j * 256) & 7;
            pb[j] = *(const float4*)&Bm[(long long)(n0 + r) * ldb + c4 * 4];
        }
    } else {
        #pragma unroll
        for (int j = 0; j < BIT; j++) {
            int i = tid + j * 256;
            int k = i / (TILE_N / 4), nc = i % (TILE_N / 4);
            pb[j] = *(const float4*)&Bm[(long long)k * ldb + n0 + nc * 4];
        }
    }
    #pragma unroll
    for (int j = 0; j < AIT; j++) {
        int r = (tid + j * 256) >> 3, c4 = (tid + j * 256) & 7;
        *(float4*)&As[r * SA + c4 * 4] = tf32r4(pa[j]);
    }
    if (TRANSB) {
        #pragma unroll
        for (int j = 0; j < BIT; j++) {
            int r = (tid + j * 256) >> 3, c4 = (tid + j * 256) & 7;
            *(float4*)&Bs[r * SA + c4 * 4] = tf32r4(pb[j]);
        }
    } else {
        #pragma unroll
        for (int j = 0; j < BIT; j++) {
            int i = tid + j * 256;
            int k = i / (TILE_N / 4), nc = i % (TILE_N / 4);
            *(float4*)&Bs[k * SB + nc * 4] = tf32r4(pb[j]);
        }
    }
    __syncthreads();

    int buf = 0;
    for (int t = 0; t < ktiles; t++) {
        // prefetch next tile
        if (t + 1 < ktiles) {
            const int k0 = (t + 1) * BK;
            #pragma unroll
            for (int j = 0; j < AIT; j++) {
                int r = (tid + j * 256) >> 3, c4 = (tid + j * 256) & 7;
                pa[j] = *(const float4*)&A[(long long)(m0 + r) * lda + k0 + c4 * 4];
            }
            if (TRANSB) {
                #pragma unroll
                for (int j = 0; j < BIT; j++) {
                    int r = (tid + j * 256) >> 3, c4 = (tid + j * 256) & 7;
                    pb[j] = *(const float4*)&Bm[(long long)(n0 + r) * ldb + k0 + c4 * 4];
                }
            } else {
                #pragma unroll
                for (int j = 0; j < BIT; j++) {
                    int i = tid + j * 256;
                    int k = i / (TILE_N / 4), nc = i % (TILE_N / 4);
                    pb[j] = *(const float4*)&Bm[(long long)(k0 + k) * ldb + n0 + nc * 4];
                }
            }
        }
        // compute 4 k-steps of 8 from smem[buf]
        const float* as = As + buf * ASTG;
        const float* bs = Bs + buf * BSTG;
        #pragma unroll
        for (int ks = 0; ks < 4; ks++) {
            const int kc = ks * 8 + (lane & 3);
            float af[4][4];
            #pragma unroll
            for (int mf = 0; mf < 4; mf++) {
                const int r = wm * 64 + mf * 16 + (lane >> 2);
                af[mf][0] = as[r * SA + kc];
                af[mf][1] = as[(r + 8) * SA + kc];
                af[mf][2] = as[r * SA + kc + 4];
                af[mf][3] = as[(r + 8) * SA + kc + 4];
            }
            float bf[NF][2];
            #pragma unroll
            for (int nf = 0; nf < NF; nf++) {
                const int c = wn * WN + nf * 8 + (lane >> 2);
                if (TRANSB) {
                    bf[nf][0] = bs[c * SA + kc];
                    bf[nf][1] = bs[c * SA + kc + 4];
                } else {
                    bf[nf][0] = bs[kc * SB + c];
                    bf[nf][1] = bs[(kc + 4) * SB + c];
                }
            }
            #pragma unroll
            for (int mf = 0; mf < 4; mf++)
                #pragma unroll
                for (int nf = 0; nf < NF; nf++)
                    mma8(acc[mf][nf], af[mf], bf[nf]);
        }
        // store prefetched tile into the other buffer
        if (t + 1 < ktiles) {
            float* ad = As + (buf ^ 1) * ASTG;
            float* bd = Bs + (buf ^ 1) * BSTG;
            #pragma unroll
            for (int j = 0; j < AIT; j++) {
                int r = (tid + j * 256) >> 3, c4 = (tid + j * 256) & 7;
                *(float4*)&ad[r * SA + c4 * 4] = tf32r4(pa[j]);
            }
            if (TRANSB) {
                #pragma unroll
                for (int j = 0; j < BIT; j++) {
                    int r = (tid + j * 256) >> 3, c4 = (tid + j * 256) & 7;
                    *(float4*)&bd[r * SA + c4 * 4] = tf32r4(pb[j]);
                }
            } else {
                #pragma unroll
                for (int j = 0; j < BIT; j++) {
                    int i = tid + j * 256;
                    int k = i / (TILE_N / 4), nc = i % (TILE_N / 4);
                    *(float4*)&bd[k * SB + nc * 4] = tf32r4(pb[j]);
                }
            }
            __syncthreads();
            buf ^= 1;
        }
    }

    // ---- epilogue ----
    const float ni = __int_as_float(0xff800000);
    #pragma unroll
    for (int mf = 0; mf < 4; mf++) {
        const int r0 = m0 + wm * 64 + mf * 16 + (lane >> 2);
        const int r1 = r0 + 8;
        #pragma unroll
        for (int nf = 0; nf < NF; nf++) {
            const int c = n0 + wn * WN + nf * 8 + 2 * (lane & 3);
            float2 v0 = make_float2(acc[mf][nf][0], acc[mf][nf][1]);
            float2 v1 = make_float2(acc[mf][nf][2], acc[mf][nf][3]);
            if (MASK) {
                v0.x = (c     <= r0) ? v0.x * scale : ni;
                v0.y = (c + 1 <= r0) ? v0.y * scale : ni;
                v1.x = (c     <= r1) ? v1.x * scale : ni;
                v1.y = (c + 1 <= r1) ? v1.y * scale : ni;
            }
            *(float2*)&C[(long long)r0 * ldc + c] = v0;
            *(float2*)&C[(long long)r1 * ldc + c] = v1;
        }
    }
}

// ---------------- softmax (unchanged, proven) ----------------
__global__ __launch_bounds__(256)
void softmax_kernel()
{
    const long long row = blockIdx.x;
    float4* p4 = (float4*)(g_P + row * SEQ);
    const int tid = threadIdx.x;
    __shared__ float red[256];

    float m = __int_as_float(0xff800000);
    #pragma unroll
    for (int i = tid; i < SEQ / 4; i += 256) {
        float4 v = p4[i];
        m = fmaxf(m, fmaxf(fmaxf(v.x, v.y), fmaxf(v.z, v.w)));
    }
    red[tid] = m; __syncthreads();
    for (int s = 128; s > 0; s >>= 1) {
        if (tid < s) red[tid] = fmaxf(red[tid], red[tid + s]);
        __syncthreads();
    }
    m = red[0];
    __syncthreads();

    float sum = 0.0f;
    #pragma unroll
    for (int i = tid; i < SEQ / 4; i += 256) {
        float4 v = p4[i];
        v.x = __expf(v.x - m); v.y = __expf(v.y - m);
        v.z = __expf(v.z - m); v.w = __expf(v.w - m);
        sum += (v.x + v.y) + (v.z + v.w);
        p4[i] = v;
    }
    red[tid] = sum; __syncthreads();
    for (int s = 128; s > 0; s >>= 1) {
        if (tid < s) red[tid] += red[tid + s];
        __syncthreads();
    }
    const float inv = 1.0f / red[0];
    __syncthreads();

    #pragma unroll
    for (int i = tid; i < SEQ / 4; i += 256) {
        float4 v = p4[i];
        v.x *= inv; v.y *= inv; v.z *= inv; v.w *= inv;
        p4[i] = v;
    }
}

// ---------------- host ----------------
extern "C" void kernel_launch(void* const* d_in, const int* in_sizes, int n_in,
                              void* d_out, int out_size)
{
    const float* x  = (const float*)d_in[0];
    const float* Wq = (const float*)d_in[1];
    const float* Wk = (const float*)d_in[2];
    const float* Wv = (const float*)d_in[3];
    const float* Wo = (const float*)d_in[4];
    float* out = (float*)d_out;

    float *Q, *K, *V, *P, *CTX;
    cudaGetSymbolAddress((void**)&Q,   g_Q);
    cudaGetSymbolAddress((void**)&K,   g_K);
    cudaGetSymbolAddress((void**)&V,   g_V);
    cudaGetSymbolAddress((void**)&P,   g_P);
    cudaGetSymbolAddress((void**)&CTX, g_C);

    // smem sizes (bytes)
    const int smNT128 = (2 * TILE_M * SA + 2 * 128 * SA) * 4;          // 73728
    const int smNN128 = (2 * TILE_M * SA + 2 * BK * (128 + 4)) * 4;    // 70656
    const int smNT64  = (2 * TILE_M * SA + 2 * 64 * SA) * 4;           // 55296

    cudaFuncSetAttribute(mm_mma<128, true,  false, false>, cudaFuncAttributeMaxDynamicSharedMemorySize, smNT128);
    cudaFuncSetAttribute(mm_mma<128, true,  true,  false>, cudaFuncAttributeMaxDynamicSharedMemorySize, smNT128);
    cudaFuncSetAttribute(mm_mma<128, false, false, true >, cudaFuncAttributeMaxDynamicSharedMemorySize, smNN128);
    cudaFuncSetAttribute(mm_mma<64,  true,  false, false>, cudaFuncAttributeMaxDynamicSharedMemorySize, smNT64);

    const dim3 blk(256);
    const float scale = 1.0f / 32.0f;   // 1/sqrt(1024)

    // 1) Q, K, V projections: [8192,1024] = x @ W^T  (NT)
    mm_mma<128, true, false, false><<<dim3(DM / 128, MTOT / 128, 1), blk, smNT128>>>(
        x, Wq, Q, DM, DM, DM, DM, 0, 0, 0, 1.0f);
    mm_mma<128, true, false, false><<<dim3(DM / 128, MTOT / 128, 1), blk, smNT128>>>(
        x, Wk, K, DM, DM, DM, DM, 0, 0, 0, 1.0f);
    mm_mma<128, true, false, false><<<dim3(DM / 128, MTOT / 128, 1), blk, smNT128>>>(
        x, Wv, V, DM, DM, DM, DM, 0, 0, 0, 1.0f);

    // 2) scores = mask(Q @ K^T) * scale  per batch  [S,S]  (NT + causal)
    mm_mma<128, true, true, false><<<dim3(SEQ / 128, SEQ / 128, BATCH), blk, smNT128>>>(
        Q, K, P, DM, DM, DM, SEQ,
        (long long)SEQ * DM, (long long)SEQ * DM, (long long)SEQ * SEQ, scale);

    // 3) row softmax (in place)
    softmax_kernel<<<BATCH * SEQ, 256>>>();

    // 4) ctx = P @ V  per batch  [S,D]  (NN + causal k-limit)
    mm_mma<128, false, false, true><<<dim3(DM / 128, SEQ / 128, BATCH), blk, smNN128>>>(
        P, V, CTX, SEQ, SEQ, DM, DM,
        (long long)SEQ * SEQ, (long long)SEQ * DM, (long long)SEQ * DM, 1.0f);

    // 5) out = ctx @ Wo^T  [8192,64]  (NT)
    mm_mma<64, true, false, false><<<dim3(DVAL / 64, MTOT / 128, 1), blk, smNT64>>>(
        CTX, Wo, out, DM, DM, DM, DVAL, 0, 0, 0, 1.0f);
}

// round 5
// speedup vs baseline: 5.8880x; 2.1205x over previous
#include <cuda_runtime.h>
#include <cuda_fp16.h>
#include <cstdint>
#include <math.h>

#define DM    1024
#define BATCH 4
#define SEQ   2048
#define DVAL  64
#define MTOT  (BATCH*SEQ)   // 8192

// ---------------- scratch (device globals; no allocs allowed) ----------------
__device__ __half g_Xh [(size_t)MTOT * DM];
__device__ __half g_Wqh[(size_t)DM * DM];
__device__ __half g_Wkh[(size_t)DM * DM];
__device__ __half g_Wvh[(size_t)DM * DM];
__device__ __half g_Woh[(size_t)DVAL * DM];
__device__ __half g_Qh [(size_t)MTOT * DM];
__device__ __half g_Kh [(size_t)MTOT * DM];
__device__ __half g_Vh [(size_t)MTOT * DM];
__device__ __half g_Ph [(size_t)BATCH * SEQ * SEQ];
__device__ __half g_Ch [(size_t)MTOT * DM];
__device__ float  g_P  [(size_t)BATCH * SEQ * SEQ];   // fp32 scores

// ---------------- helpers ----------------
__device__ __forceinline__ uint32_t smem_u32(const void* p) {
    uint32_t a;
    asm("{ .reg .u64 t; cvta.to.shared.u64 t, %1; cvt.u32.u64 %0, t; }" : "=r"(a) : "l"(p));
    return a;
}
#define SWZ(o) ((o) ^ (((o) >> 3) & 0x70))

#define CPA16(dst, src) \
    asm volatile("cp.async.cg.shared.global [%0], [%1], 16;" :: "r"(dst), "l"(src) : "memory")
#define CP_COMMIT() asm volatile("cp.async.commit_group;" ::: "memory")
#define CP_WAIT1()  asm volatile("cp.async.wait_group 1;" ::: "memory")

#define LDSM_X4(d0, d1, d2, d3, a) \
    asm volatile("ldmatrix.sync.aligned.m8n8.x4.shared.b16 {%0,%1,%2,%3}, [%4];" \
        : "=r"(d0), "=r"(d1), "=r"(d2), "=r"(d3) : "r"(a))
#define LDSM_X4T(d0, d1, d2, d3, a) \
    asm volatile("ldmatrix.sync.aligned.m8n8.x4.trans.shared.b16 {%0,%1,%2,%3}, [%4];" \
        : "=r"(d0), "=r"(d1), "=r"(d2), "=r"(d3) : "r"(a))

__device__ __forceinline__ void mma16(float* c, const uint32_t* a, const uint32_t* b) {
    asm volatile(
        "mma.sync.aligned.m16n8k16.row.col.f32.f16.f16.f32 "
        "{%0,%1,%2,%3}, {%4,%5,%6,%7}, {%8,%9}, {%0,%1,%2,%3};"
        : "+f"(c[0]), "+f"(c[1]), "+f"(c[2]), "+f"(c[3])
        : "r"(a[0]), "r"(a[1]), "r"(a[2]), "r"(a[3]), "r"(b[0]), "r"(b[1]));
}

// ---------------- fp16 tensor-core GEMM ----------------
// C[M,N] = A[M,K](half,k-major) * B.  TRANSB: B[N,K].  else B[K,N].
// MASK: causal+scale epilogue on fp32 C; skip fully-masked tiles.
// KLIMIT: truncate K at m0+128 (causal P exact zeros beyond).
// HOUT: write __half C (else fp32).
template<int TILE_N, bool TRANSB, bool MASK, bool KLIMIT, bool HOUT>
__global__ __launch_bounds__(256, 1)
void mm_h(const __half* __restrict__ A, const __half* __restrict__ Bm,
          void* __restrict__ Cv, int K, int lda, int ldb, int ldc,
          long long zsA, long long zsB, long long zsC, float scale)
{
    extern __shared__ __align__(16) char smc[];
    constexpr int STAGES = 3;
    constexpr int ASTG = 128 * 128;                    // bytes per A stage (128 rows x 64 halves)
    constexpr int SBH  = TILE_N + 8;                   // NN: halves per k-row
    constexpr int BSTG = TRANSB ? TILE_N * 128 : 64 * SBH * 2;
    constexpr int WN = TILE_N / 4;
    constexpr int NF = WN / 8;

    const int tid = threadIdx.x, lane = tid & 31, wid = tid >> 5;
    const int wm = wid & 1, wn = wid >> 1;
    const int m0 = blockIdx.y * 128;
    const int n0 = blockIdx.x * TILE_N;

    A  += (long long)blockIdx.z * zsA;
    Bm += (long long)blockIdx.z * zsB;
    float*  Cf = (float*)Cv  + (long long)blockIdx.z * zsC;
    __half* Ch = (__half*)Cv + (long long)blockIdx.z * zsC;

    if (MASK && n0 > m0 + 127) {
        const float ni = __int_as_float(0xff800000);
        float4 v = make_float4(ni, ni, ni, ni);
        for (int i = tid; i < 128 * TILE_N / 4; i += 256) {
            int r = i / (TILE_N / 4), c4 = i % (TILE_N / 4);
            *(float4*)&Cf[(long long)(m0 + r) * ldc + n0 + c4 * 4] = v;
        }
        return;
    }

    const uint32_t aB0 = smem_u32(smc);
    const uint32_t bB0 = aB0 + STAGES * ASTG;

    const int ktiles = KLIMIT ? (m0 + 128) / 64 : K / 64;

    float acc[4][NF][4];
    #pragma unroll
    for (int i = 0; i < 4; i++)
        #pragma unroll
        for (int j = 0; j < NF; j++)
            #pragma unroll
            for (int q = 0; q < 4; q++) acc[i][j][q] = 0.0f;

    // stage loader
    auto load_stage = [&](int t, int s) {
        const int k0 = t * 64;
        #pragma unroll
        for (int j = 0; j < 4; j++) {
            int i = tid + j * 256, r = i >> 3, sg = i & 7;
            const __half* src = A + (long long)(m0 + r) * lda + k0 + sg * 8;
            CPA16(aB0 + s * ASTG + SWZ(r * 128 + sg * 16), src);
        }
        if (TRANSB) {
            #pragma unroll
            for (int j = 0; j < TILE_N * 8 / 256; j++) {
                int i = tid + j * 256, r = i >> 3, sg = i & 7;
                const __half* src = Bm + (long long)(n0 + r) * ldb + k0 + sg * 8;
                CPA16(bB0 + s * BSTG + SWZ(r * 128 + sg * 16), src);
            }
        } else {
            #pragma unroll
            for (int j = 0; j < 64 * (TILE_N / 8) / 256; j++) {
                int i = tid + j * 256, kk = i / (TILE_N / 8), sg = i % (TILE_N / 8);
                const __half* src = Bm + (long long)(k0 + kk) * ldb + n0 + sg * 8;
                CPA16(bB0 + s * BSTG + kk * (SBH * 2) + sg * 16, src);
            }
        }
    };

    // prologue: stages 0,1
    #pragma unroll
    for (int s = 0; s < STAGES - 1; s++) {
        if (s < ktiles) load_stage(s, s);
        CP_COMMIT();
    }

    for (int t = 0; t < ktiles; t++) {
        const int tn = t + STAGES - 1;
        if (tn < ktiles) load_stage(tn, tn % STAGES);
        CP_COMMIT();
        CP_WAIT1();
        __syncthreads();

        const uint32_t aS = aB0 + (t % STAGES) * ASTG;
        const uint32_t bS = bB0 + (t % STAGES) * BSTG;

        #pragma unroll
        for (int ks = 0; ks < 4; ks++) {
            uint32_t a[4][4];
            #pragma unroll
            for (int mf = 0; mf < 4; mf++) {
                int row = wm * 64 + mf * 16 + ((lane >> 3) & 1) * 8 + (lane & 7);
                uint32_t ad = aS + SWZ(row * 128 + ks * 32 + (lane >> 4) * 16);
                LDSM_X4(a[mf][0], a[mf][1], a[mf][2], a[mf][3], ad);
            }
            uint32_t b[NF][2];
            #pragma unroll
            for (int p = 0; p < NF / 2; p++) {
                uint32_t d0, d1, d2, d3;
                if (TRANSB) {
                    int row = wn * WN + p * 16 + (lane >> 4) * 8 + (lane & 7);
                    uint32_t bd = bS + SWZ(row * 128 + ks * 32 + ((lane >> 3) & 1) * 16);
                    LDSM_X4(d0, d1, d2, d3, bd);
                } else {
                    int kr  = ks * 16 + ((lane >> 3) & 1) * 8 + (lane & 7);
                    int col = wn * WN + p * 16 + (lane >> 4) * 8;
                    uint32_t bd = bS + kr * (SBH * 2) + col * 2;
                    LDSM_X4T(d0, d1, d2, d3, bd);
                }
                b[2 * p][0] = d0; b[2 * p][1] = d1;
                b[2 * p + 1][0] = d2; b[2 * p + 1][1] = d3;
            }
            #pragma unroll
            for (int mf = 0; mf < 4; mf++)
                #pragma unroll
                for (int nf = 0; nf < NF; nf++)
                    mma16(acc[mf][nf], a[mf], b[nf]);
        }
        __syncthreads();
    }

    // ---- epilogue ----
    const float ni = __int_as_float(0xff800000);
    #pragma unroll
    for (int mf = 0; mf < 4; mf++) {
        const int r0 = m0 + wm * 64 + mf * 16 + (lane >> 2);
        const int r1 = r0 + 8;
        #pragma unroll
        for (int nf = 0; nf < NF; nf++) {
            const int c = n0 + wn * WN + nf * 8 + 2 * (lane & 3);
            float2 v0 = make_float2(acc[mf][nf][0], acc[mf][nf][1]);
            float2 v1 = make_float2(acc[mf][nf][2], acc[mf][nf][3]);
            if (MASK) {
                v0.x = (c     <= r0) ? v0.x * scale : ni;
                v0.y = (c + 1 <= r0) ? v0.y * scale : ni;
                v1.x = (c     <= r1) ? v1.x * scale : ni;
                v1.y = (c + 1 <= r1) ? v1.y * scale : ni;
            }
            if (HOUT) {
                *(__half2*)&Ch[(long long)r0 * ldc + c] = __floats2half2_rn(v0.x, v0.y);
                *(__half2*)&Ch[(long long)r1 * ldc + c] = __floats2half2_rn(v1.x, v1.y);
            } else {
                *(float2*)&Cf[(long long)r0 * ldc + c] = v0;
                *(float2*)&Cf[(long long)r1 * ldc + c] = v1;
            }
        }
    }
}

// ---------------- fp32 -> fp16 pre-pass ----------------
__global__ __launch_bounds__(256)
void f2h_kernel(const float4* __restrict__ src, __half2* __restrict__ dst, int n4)
{
    int i = blockIdx.x * 256 + threadIdx.x;
    if (i < n4) {
        float4 v = src[i];
        dst[2 * i]     = __floats2half2_rn(v.x, v.y);
        dst[2 * i + 1] = __floats2half2_rn(v.z, v.w);
    }
}

// ---------------- softmax: fp32 scores -> fp16 probs ----------------
__global__ __launch_bounds__(256)
void softmax_kernel()
{
    const long long row = blockIdx.x;
    const float4* p4 = (const float4*)(g_P + row * SEQ);
    __half2* o2 = (__half2*)(g_Ph + row * SEQ);
    const int tid = threadIdx.x;
    __shared__ float red[256];

    float m = __int_as_float(0xff800000);
    #pragma unroll
    for (int i = tid; i < SEQ / 4; i += 256) {
        float4 v = p4[i];
        m = fmaxf(m, fmaxf(fmaxf(v.x, v.y), fmaxf(v.z, v.w)));
    }
    red[tid] = m; __syncthreads();
    for (int s = 128; s > 0; s >>= 1) {
        if (tid < s) red[tid] = fmaxf(red[tid], red[tid + s]);
        __syncthreads();
    }
    m = red[0];
    __syncthreads();

    float sum = 0.0f;
    #pragma unroll
    for (int i = tid; i < SEQ / 4; i += 256) {
        float4 v = p4[i];
        v.x = __expf(v.x - m); v.y = __expf(v.y - m);
        v.z = __expf(v.z - m); v.w = __expf(v.w - m);
        sum += (v.x + v.y) + (v.z + v.w);
        red[tid] = 0.0f;  // placeholder to keep smem live
        ((float4*)(g_P + row * SEQ))[i] = v;   // stash exp for second pass
    }
    red[tid] = sum; __syncthreads();
    for (int s = 128; s > 0; s >>= 1) {
        if (tid < s) red[tid] += red[tid + s];
        __syncthreads();
    }
    const float inv = 1.0f / red[0];
    __syncthreads();

    #pragma unroll
    for (int i = tid; i < SEQ / 4; i += 256) {
        float4 v = ((const float4*)(g_P + row * SEQ))[i];
        o2[2 * i]     = __floats2half2_rn(v.x * inv, v.y * inv);
        o2[2 * i + 1] = __floats2half2_rn(v.z * inv, v.w * inv);
    }
}

// ---------------- host ----------------
extern "C" void kernel_launch(void* const* d_in, const int* in_sizes, int n_in,
                              void* d_out, int out_size)
{
    const float* x  = (const float*)d_in[0];
    const float* Wq = (const float*)d_in[1];
    const float* Wk = (const float*)d_in[2];
    const float* Wv = (const float*)d_in[3];
    const float* Wo = (const float*)d_in[4];
    float* out = (float*)d_out;

    __half *Xh, *Wqh, *Wkh, *Wvh, *Woh, *Qh, *Kh, *Vh, *Ph, *Chx;
    float* P;
    cudaGetSymbolAddress((void**)&Xh,  g_Xh);
    cudaGetSymbolAddress((void**)&Wqh, g_Wqh);
    cudaGetSymbolAddress((void**)&Wkh, g_Wkh);
    cudaGetSymbolAddress((void**)&Wvh, g_Wvh);
    cudaGetSymbolAddress((void**)&Woh, g_Woh);
    cudaGetSymbolAddress((void**)&Qh,  g_Qh);
    cudaGetSymbolAddress((void**)&Kh,  g_Kh);
    cudaGetSymbolAddress((void**)&Vh,  g_Vh);
    cudaGetSymbolAddress((void**)&Ph,  g_Ph);
    cudaGetSymbolAddress((void**)&Chx, g_Ch);
    cudaGetSymbolAddress((void**)&P,   g_P);

    const int smNT128 = 3 * (16384 + 128 * 128);        // 98304
    const int smNN128 = 3 * (16384 + 64 * (128 + 8) * 2); // 101376
    const int smNT64  = 3 * (16384 + 64 * 128);         // 73728
    cudaFuncSetAttribute(mm_h<128, true,  false, false, true >, cudaFuncAttributeMaxDynamicSharedMemorySize, smNT128);
    cudaFuncSetAttribute(mm_h<128, true,  true,  false, false>, cudaFuncAttributeMaxDynamicSharedMemorySize, smNT128);
    cudaFuncSetAttribute(mm_h<128, false, false, true,  true >, cudaFuncAttributeMaxDynamicSharedMemorySize, smNN128);
    cudaFuncSetAttribute(mm_h<64,  true,  false, false, false>, cudaFuncAttributeMaxDynamicSharedMemorySize, smNT64);

    // 0) round inputs to fp16
    f2h_kernel<<<(MTOT * DM / 4 + 255) / 256, 256>>>((const float4*)x,  (__half2*)Xh,  MTOT * DM / 4);
    f2h_kernel<<<(DM * DM / 4 + 255) / 256, 256>>>((const float4*)Wq, (__half2*)Wqh, DM * DM / 4);
    f2h_kernel<<<(DM * DM / 4 + 255) / 256, 256>>>((const float4*)Wk, (__half2*)Wkh, DM * DM / 4);
    f2h_kernel<<<(DM * DM / 4 + 255) / 256, 256>>>((const float4*)Wv, (__half2*)Wvh, DM * DM / 4);
    f2h_kernel<<<(DVAL * DM / 4 + 255) / 256, 256>>>((const float4*)Wo, (__half2*)Woh, DVAL * DM / 4);

    const dim3 blk(256);
    const float scale = 1.0f / 32.0f;   // 1/sqrt(1024)

    // 1) Q, K, V projections (NT, half out)
    mm_h<128, true, false, false, true><<<dim3(DM / 128, MTOT / 128, 1), blk, smNT128>>>(
        Xh, Wqh, Qh, DM, DM, DM, DM, 0, 0, 0, 1.0f);
    mm_h<128, true, false, false, true><<<dim3(DM / 128, MTOT / 128, 1), blk, smNT128>>>(
        Xh, Wkh, Kh, DM, DM, DM, DM, 0, 0, 0, 1.0f);
    mm_h<128, true, false, false, true><<<dim3(DM / 128, MTOT / 128, 1), blk, smNT128>>>(
        Xh, Wvh, Vh, DM, DM, DM, DM, 0, 0, 0, 1.0f);

    // 2) scores = mask(Q @ K^T) * scale  (NT + causal, fp32 out)
    mm_h<128, true, true, false, false><<<dim3(SEQ / 128, SEQ / 128, BATCH), blk, smNT128>>>(
        Qh, Kh, P, DM, DM, DM, SEQ,
        (long long)SEQ * DM, (long long)SEQ * DM, (long long)SEQ * SEQ, scale);

    // 3) softmax: fp32 scores -> fp16 probs
    softmax_kernel<<<BATCH * SEQ, 256>>>();

    // 4) ctx = P @ V  (NN + causal k-limit, half out)
    mm_h<128, false, false, true, true><<<dim3(DM / 128, SEQ / 128, BATCH), blk, smNN128>>>(
        Ph, Vh, Chx, SEQ, SEQ, DM, DM,
        (long long)SEQ * SEQ, (long long)SEQ * DM, (long long)SEQ * DM, 1.0f);

    // 5) out = ctx @ Wo^T  (NT, fp32 out)
    mm_h<64, true, false, false, false><<<dim3(DVAL / 64, MTOT / 128, 1), blk, smNT64>>>(
        Chx, Woh, out, DM, DM, DM, DVAL, 0, 0, 0, 1.0f);
}

// round 6
// speedup vs baseline: 6.3521x; 1.0788x over previous
#include <cuda_runtime.h>
#include <cuda_fp16.h>
#include <cstdint>
#include <math.h>

#define DM    1024
#define BATCH 4
#define SEQ   2048
#define DVAL  64
#define MTOT  (BATCH*SEQ)   // 8192

// ---------------- scratch (device globals; no allocs allowed) ----------------
__device__ __half g_Xh [(size_t)MTOT * DM];
__device__ __half g_Wqh[(size_t)DM * DM];
__device__ __half g_Wkh[(size_t)DM * DM];
__device__ __half g_Wvh[(size_t)DM * DM];
__device__ __half g_Woh[(size_t)DVAL * DM];
__device__ __half g_Qh [(size_t)MTOT * DM];
__device__ __half g_Kh [(size_t)MTOT * DM];
__device__ __half g_Vh [(size_t)MTOT * DM];
__device__ __half g_Ph [(size_t)BATCH * SEQ * SEQ];
__device__ __half g_Ch [(size_t)MTOT * DM];
__device__ float  g_P  [(size_t)BATCH * SEQ * SEQ];   // fp32 scores (lower-tri tiles only)

// ---------------- helpers ----------------
__device__ __forceinline__ uint32_t smem_u32(const void* p) {
    uint32_t a;
    asm("{ .reg .u64 t; cvta.to.shared.u64 t, %1; cvt.u32.u64 %0, t; }" : "=r"(a) : "l"(p));
    return a;
}
#define SWZ(o) ((o) ^ (((o) >> 3) & 0x70))

#define CPA16(dst, src) \
    asm volatile("cp.async.cg.shared.global [%0], [%1], 16;" :: "r"(dst), "l"(src) : "memory")
#define CP_COMMIT() asm volatile("cp.async.commit_group;" ::: "memory")
#define CP_WAIT1()  asm volatile("cp.async.wait_group 1;" ::: "memory")

#define LDSM_X4(d0, d1, d2, d3, a) \
    asm volatile("ldmatrix.sync.aligned.m8n8.x4.shared.b16 {%0,%1,%2,%3}, [%4];" \
        : "=r"(d0), "=r"(d1), "=r"(d2), "=r"(d3) : "r"(a))
#define LDSM_X4T(d0, d1, d2, d3, a) \
    asm volatile("ldmatrix.sync.aligned.m8n8.x4.trans.shared.b16 {%0,%1,%2,%3}, [%4];" \
        : "=r"(d0), "=r"(d1), "=r"(d2), "=r"(d3) : "r"(a))

__device__ __forceinline__ void mma16(float* c, const uint32_t* a, const uint32_t* b) {
    asm volatile(
        "mma.sync.aligned.m16n8k16.row.col.f32.f16.f16.f32 "
        "{%0,%1,%2,%3}, {%4,%5,%6,%7}, {%8,%9}, {%0,%1,%2,%3};"
        : "+f"(c[0]), "+f"(c[1]), "+f"(c[2]), "+f"(c[3])
        : "r"(a[0]), "r"(a[1]), "r"(a[2]), "r"(a[3]), "r"(b[0]), "r"(b[1]));
}

// ---------------- fp16 tensor-core GEMM ----------------
// C[M,N] = A[M,K](half,k-major) * B.  TRANSB: B[N,K].  else B[K,N].
// MASK: causal+scale epilogue on fp32 C; fully-masked tiles do NOTHING (no write).
// KLIMIT: truncate K at m0+128 (causal P exact zeros beyond).
// HOUT: write __half C (else fp32).
template<int TILE_N, bool TRANSB, bool MASK, bool KLIMIT, bool HOUT>
__global__ __launch_bounds__(256, 1)
void mm_h(const __half* __restrict__ A, const __half* __restrict__ Bm,
          void* __restrict__ Cv, int K, int lda, int ldb, int ldc,
          long long zsA, long long zsB, long long zsC, float scale)
{
    extern __shared__ __align__(16) char smc[];
    constexpr int STAGES = 3;
    constexpr int ASTG = 128 * 128;                    // bytes per A stage (128 rows x 64 halves)
    constexpr int SBH  = TILE_N + 8;                   // NN: halves per k-row
    constexpr int BSTG = TRANSB ? TILE_N * 128 : 64 * SBH * 2;
    constexpr int WN = TILE_N / 4;
    constexpr int NF = WN / 8;

    const int tid = threadIdx.x, lane = tid & 31, wid = tid >> 5;
    const int wm = wid & 1, wn = wid >> 1;
    const int m0 = blockIdx.y * 128;
    const int n0 = blockIdx.x * TILE_N;

    if (MASK && n0 > m0 + 127) return;   // never read by causal softmax

    A  += (long long)blockIdx.z * zsA;
    Bm += (long long)blockIdx.z * zsB;
    float*  Cf = (float*)Cv  + (long long)blockIdx.z * zsC;
    __half* Ch = (__half*)Cv + (long long)blockIdx.z * zsC;

    const uint32_t aB0 = smem_u32(smc);
    const uint32_t bB0 = aB0 + STAGES * ASTG;

    const int ktiles = KLIMIT ? (m0 + 128) / 64 : K / 64;

    float acc[4][NF][4];
    #pragma unroll
    for (int i = 0; i < 4; i++)
        #pragma unroll
        for (int j = 0; j < NF; j++)
            #pragma unroll
            for (int q = 0; q < 4; q++) acc[i][j][q] = 0.0f;

    auto load_stage = [&](int t, int s) {
        const int k0 = t * 64;
        #pragma unroll
        for (int j = 0; j < 4; j++) {
            int i = tid + j * 256, r = i >> 3, sg = i & 7;
            const __half* src = A + (long long)(m0 + r) * lda + k0 + sg * 8;
            CPA16(aB0 + s * ASTG + SWZ(r * 128 + sg * 16), src);
        }
        if (TRANSB) {
            #pragma unroll
            for (int j = 0; j < TILE_N * 8 / 256; j++) {
                int i = tid + j * 256, r = i >> 3, sg = i & 7;
                const __half* src = Bm + (long long)(n0 + r) * ldb + k0 + sg * 8;
                CPA16(bB0 + s * BSTG + SWZ(r * 128 + sg * 16), src);
            }
        } else {
            #pragma unroll
            for (int j = 0; j < 64 * (TILE_N / 8) / 256; j++) {
                int i = tid + j * 256, kk = i / (TILE_N / 8), sg = i % (TILE_N / 8);
                const __half* src = Bm + (long long)(k0 + kk) * ldb + n0 + sg * 8;
                CPA16(bB0 + s * BSTG + kk * (SBH * 2) + sg * 16, src);
            }
        }
    };

    #pragma unroll
    for (int s = 0; s < STAGES - 1; s++) {
        if (s < ktiles) load_stage(s, s);
        CP_COMMIT();
    }

    for (int t = 0; t < ktiles; t++) {
        const int tn = t + STAGES - 1;
        if (tn < ktiles) load_stage(tn, tn % STAGES);
        CP_COMMIT();
        CP_WAIT1();
        __syncthreads();

        const uint32_t aS = aB0 + (t % STAGES) * ASTG;
        const uint32_t bS = bB0 + (t % STAGES) * BSTG;

        #pragma unroll
        for (int ks = 0; ks < 4; ks++) {
            uint32_t a[4][4];
            #pragma unroll
            for (int mf = 0; mf < 4; mf++) {
                int row = wm * 64 + mf * 16 + ((lane >> 3) & 1) * 8 + (lane & 7);
                uint32_t ad = aS + SWZ(row * 128 + ks * 32 + (lane >> 4) * 16);
                LDSM_X4(a[mf][0], a[mf][1], a[mf][2], a[mf][3], ad);
            }
            uint32_t b[NF][2];
            #pragma unroll
            for (int p = 0; p < NF / 2; p++) {
                uint32_t d0, d1, d2, d3;
                if (TRANSB) {
                    int row = wn * WN + p * 16 + (lane >> 4) * 8 + (lane & 7);
                    uint32_t bd = bS + SWZ(row * 128 + ks * 32 + ((lane >> 3) & 1) * 16);
                    LDSM_X4(d0, d1, d2, d3, bd);
                } else {
                    int kr  = ks * 16 + ((lane >> 3) & 1) * 8 + (lane & 7);
                    int col = wn * WN + p * 16 + (lane >> 4) * 8;
                    uint32_t bd = bS + kr * (SBH * 2) + col * 2;
                    LDSM_X4T(d0, d1, d2, d3, bd);
                }
                b[2 * p][0] = d0; b[2 * p][1] = d1;
                b[2 * p + 1][0] = d2; b[2 * p + 1][1] = d3;
            }
            #pragma unroll
            for (int mf = 0; mf < 4; mf++)
                #pragma unroll
                for (int nf = 0; nf < NF; nf++)
                    mma16(acc[mf][nf], a[mf], b[nf]);
        }
        __syncthreads();
    }

    // ---- epilogue ----
    const float ni = __int_as_float(0xff800000);
    #pragma unroll
    for (int mf = 0; mf < 4; mf++) {
        const int r0 = m0 + wm * 64 + mf * 16 + (lane >> 2);
        const int r1 = r0 + 8;
        #pragma unroll
        for (int nf = 0; nf < NF; nf++) {
            const int c = n0 + wn * WN + nf * 8 + 2 * (lane & 3);
            float2 v0 = make_float2(acc[mf][nf][0], acc[mf][nf][1]);
            float2 v1 = make_float2(acc[mf][nf][2], acc[mf][nf][3]);
            if (MASK) {
                v0.x = (c     <= r0) ? v0.x * scale : ni;
                v0.y = (c + 1 <= r0) ? v0.y * scale : ni;
                v1.x = (c     <= r1) ? v1.x * scale : ni;
                v1.y = (c + 1 <= r1) ? v1.y * scale : ni;
            }
            if (HOUT) {
                *(__half2*)&Ch[(long long)r0 * ldc + c] = __floats2half2_rn(v0.x, v0.y);
                *(__half2*)&Ch[(long long)r1 * ldc + c] = __floats2half2_rn(v1.x, v1.y);
            } else {
                *(float2*)&Cf[(long long)r0 * ldc + c] = v0;
                *(float2*)&Cf[(long long)r1 * ldc + c] = v1;
            }
        }
    }
}

// ---------------- fp32 -> fp16 pre-pass ----------------
__global__ __launch_bounds__(256)
void f2h_kernel(const float4* __restrict__ src, __half2* __restrict__ dst, int n4)
{
    int i = blockIdx.x * 256 + threadIdx.x;
    if (i < n4) {
        float4 v = src[i];
        dst[2 * i]     = __floats2half2_rn(v.x, v.y);
        dst[2 * i + 1] = __floats2half2_rn(v.z, v.w);
    }
}

// ---------------- causal softmax: fp32 scores -> fp16 probs, single pass ----------------
// Row r only has valid logits in [0, r]; rows of a 128-tile all read/write [0, (r|127)+1),
// which exactly matches PV's KLIMIT read window. Upper P tiles are never touched.
__global__ __launch_bounds__(256)
void softmax_kernel()
{
    const long long row = blockIdx.x;
    const int r = (int)(row & (SEQ - 1));
    const int C4 = ((r | 127) + 1) >> 2;          // float4 count (<= 512)
    const float4* p4 = (const float4*)(g_P + row * SEQ);
    __half2* o2 = (__half2*)(g_Ph + row * SEQ);
    const int tid = threadIdx.x;
    __shared__ float red[256];

    float4 v[2];
    float m = __int_as_float(0xff800000);
    #pragma unroll
    for (int j = 0; j < 2; j++) {
        int i = tid + j * 256;
        if (i < C4) {
            v[j] = p4[i];
            m = fmaxf(m, fmaxf(fmaxf(v[j].x, v[j].y), fmaxf(v[j].z, v[j].w)));
        }
    }
    red[tid] = m; __syncthreads();
    for (int s = 128; s > 0; s >>= 1) {
        if (tid < s) red[tid] = fmaxf(red[tid], red[tid + s]);
        __syncthreads();
    }
    m = red[0];
    __syncthreads();

    float sum = 0.0f;
    #pragma unroll
    for (int j = 0; j < 2; j++) {
        int i = tid + j * 256;
        if (i < C4) {
            v[j].x = __expf(v[j].x - m); v[j].y = __expf(v[j].y - m);
            v[j].z = __expf(v[j].z - m); v[j].w = __expf(v[j].w - m);
            sum += (v[j].x + v[j].y) + (v[j].z + v[j].w);
        }
    }
    red[tid] = sum; __syncthreads();
    for (int s = 128; s > 0; s >>= 1) {
        if (tid < s) red[tid] += red[tid + s];
        __syncthreads();
    }
    const float inv = 1.0f / red[0];

    #pragma unroll
    for (int j = 0; j < 2; j++) {
        int i = tid + j * 256;
        if (i < C4) {
            o2[2 * i]     = __floats2half2_rn(v[j].x * inv, v[j].y * inv);
            o2[2 * i + 1] = __floats2half2_rn(v[j].z * inv, v[j].w * inv);
        }
    }
}

// ---------------- host ----------------
extern "C" void kernel_launch(void* const* d_in, const int* in_sizes, int n_in,
                              void* d_out, int out_size)
{
    const float* x  = (const float*)d_in[0];
    const float* Wq = (const float*)d_in[1];
    const float* Wk = (const float*)d_in[2];
    const float* Wv = (const float*)d_in[3];
    const float* Wo = (const float*)d_in[4];
    float* out = (float*)d_out;

    __half *Xh, *Wqh, *Wkh, *Wvh, *Woh, *Qh, *Kh, *Vh, *Ph, *Chx;
    float* P;
    cudaGetSymbolAddress((void**)&Xh,  g_Xh);
    cudaGetSymbolAddress((void**)&Wqh, g_Wqh);
    cudaGetSymbolAddress((void**)&Wkh, g_Wkh);
    cudaGetSymbolAddress((void**)&Wvh, g_Wvh);
    cudaGetSymbolAddress((void**)&Woh, g_Woh);
    cudaGetSymbolAddress((void**)&Qh,  g_Qh);
    cudaGetSymbolAddress((void**)&Kh,  g_Kh);
    cudaGetSymbolAddress((void**)&Vh,  g_Vh);
    cudaGetSymbolAddress((void**)&Ph,  g_Ph);
    cudaGetSymbolAddress((void**)&Chx, g_Ch);
    cudaGetSymbolAddress((void**)&P,   g_P);

    const int smNT256 = 3 * (16384 + 256 * 128);           // 147456
    const int smNN256 = 3 * (16384 + 64 * (256 + 8) * 2);  // 150528
    const int smNT64  = 3 * (16384 + 64 * 128);            // 73728
    cudaFuncSetAttribute(mm_h<256, true,  false, false, true >, cudaFuncAttributeMaxDynamicSharedMemorySize, smNT256);
    cudaFuncSetAttribute(mm_h<256, true,  true,  false, false>, cudaFuncAttributeMaxDynamicSharedMemorySize, smNT256);
    cudaFuncSetAttribute(mm_h<256, false, false, true,  true >, cudaFuncAttributeMaxDynamicSharedMemorySize, smNN256);
    cudaFuncSetAttribute(mm_h<64,  true,  false, false, false>, cudaFuncAttributeMaxDynamicSharedMemorySize, smNT64);

    // 0) round inputs to fp16
    f2h_kernel<<<(MTOT * DM / 4 + 255) / 256, 256>>>((const float4*)x,  (__half2*)Xh,  MTOT * DM / 4);
    f2h_kernel<<<(DM * DM / 4 + 255) / 256, 256>>>((const float4*)Wq, (__half2*)Wqh, DM * DM / 4);
    f2h_kernel<<<(DM * DM / 4 + 255) / 256, 256>>>((const float4*)Wk, (__half2*)Wkh, DM * DM / 4);
    f2h_kernel<<<(DM * DM / 4 + 255) / 256, 256>>>((const float4*)Wv, (__half2*)Wvh, DM * DM / 4);
    f2h_kernel<<<(DVAL * DM / 4 + 255) / 256, 256>>>((const float4*)Wo, (__half2*)Woh, DVAL * DM / 4);

    const dim3 blk(256);
    const float scale = 1.0f / 32.0f;   // 1/sqrt(1024)

    // 1) Q, K, V projections (NT, half out), 128x256 tiles
    mm_h<256, true, false, false, true><<<dim3(DM / 256, MTOT / 128, 1), blk, smNT256>>>(
        Xh, Wqh, Qh, DM, DM, DM, DM, 0, 0, 0, 1.0f);
    mm_h<256, true, false, false, true><<<dim3(DM / 256, MTOT / 128, 1), blk, smNT256>>>(
        Xh, Wkh, Kh, DM, DM, DM, DM, 0, 0, 0, 1.0f);
    mm_h<256, true, false, false, true><<<dim3(DM / 256, MTOT / 128, 1), blk, smNT256>>>(
        Xh, Wvh, Vh, DM, DM, DM, DM, 0, 0, 0, 1.0f);

    // 2) scores = mask(Q @ K^T) * scale  (NT + causal, fp32 out, lower tiles only)
    mm_h<256, true, true, false, false><<<dim3(SEQ / 256, SEQ / 128, BATCH), blk, smNT256>>>(
        Qh, Kh, P, DM, DM, DM, SEQ,
        (long long)SEQ * DM, (long long)SEQ * DM, (long long)SEQ * SEQ, scale);

    // 3) causal softmax: fp32 scores -> fp16 probs (single pass)
    softmax_kernel<<<BATCH * SEQ, 256>>>();

    // 4) ctx = P @ V  (NN + causal k-limit, half out)
    mm_h<256, false, false, true, true><<<dim3(DM / 256, SEQ / 128, BATCH), blk, smNN256>>>(
        Ph, Vh, Chx, SEQ, SEQ, DM, DM,
        (long long)SEQ * SEQ, (long long)SEQ * DM, (long long)SEQ * DM, 1.0f);

    // 5) out = ctx @ Wo^T  (NT, fp32 out)
    mm_h<64, true, false, false, false><<<dim3(DVAL / 64, MTOT / 128, 1), blk, smNT64>>>(
        Chx, Woh, out, DM, DM, DM, DVAL, 0, 0, 0, 1.0f);
}

// round 7
// speedup vs baseline: 6.9360x; 1.0919x over previous
#include <cuda_runtime.h>
#include <cuda_fp16.h>
#include <cstdint>
#include <math.h>

#define DM    1024
#define BATCH 4
#define SEQ   2048
#define DVAL  64
#define MTOT  (BATCH*SEQ)   // 8192

// ---------------- scratch (device globals; no allocs allowed) ----------------
__device__ __half g_Xh [(size_t)MTOT * DM];
__device__ __half g_Wqh[(size_t)DM * DM];
__device__ __half g_Wkh[(size_t)DM * DM];
__device__ __half g_Wvh[(size_t)DM * DM];
__device__ __half g_Woh[(size_t)DVAL * DM];
__device__ __half g_Qh [(size_t)MTOT * DM];
__device__ __half g_Kh [(size_t)MTOT * DM];
__device__ __half g_Vh [(size_t)MTOT * DM];
__device__ __half g_Ph [(size_t)BATCH * SEQ * SEQ];
__device__ __half g_Ch [(size_t)MTOT * DM];
__device__ float  g_P  [(size_t)BATCH * SEQ * SEQ];   // fp32 scores (lower-tri tiles only)

// ---------------- helpers ----------------
__device__ __forceinline__ uint32_t smem_u32(const void* p) {
    uint32_t a;
    asm("{ .reg .u64 t; cvta.to.shared.u64 t, %1; cvt.u32.u64 %0, t; }" : "=r"(a) : "l"(p));
    return a;
}
#define SWZ(o) ((o) ^ (((o) >> 3) & 0x70))

#define CPA16(dst, src) \
    asm volatile("cp.async.cg.shared.global [%0], [%1], 16;" :: "r"(dst), "l"(src) : "memory")
#define CP_COMMIT() asm volatile("cp.async.commit_group;" ::: "memory")
#define CP_WAIT1()  asm volatile("cp.async.wait_group 1;" ::: "memory")

#define LDSM_X4(d0, d1, d2, d3, a) \
    asm volatile("ldmatrix.sync.aligned.m8n8.x4.shared.b16 {%0,%1,%2,%3}, [%4];" \
        : "=r"(d0), "=r"(d1), "=r"(d2), "=r"(d3) : "r"(a))
#define LDSM_X4T(d0, d1, d2, d3, a) \
    asm volatile("ldmatrix.sync.aligned.m8n8.x4.trans.shared.b16 {%0,%1,%2,%3}, [%4];" \
        : "=r"(d0), "=r"(d1), "=r"(d2), "=r"(d3) : "r"(a))

__device__ __forceinline__ void mma16(float* c, const uint32_t* a, const uint32_t* b) {
    asm volatile(
        "mma.sync.aligned.m16n8k16.row.col.f32.f16.f16.f32 "
        "{%0,%1,%2,%3}, {%4,%5,%6,%7}, {%8,%9}, {%0,%1,%2,%3};"
        : "+f"(c[0]), "+f"(c[1]), "+f"(c[2]), "+f"(c[3])
        : "r"(a[0]), "r"(a[1]), "r"(a[2]), "r"(a[3]), "r"(b[0]), "r"(b[1]));
}

// ---------------- fp16 tensor-core GEMM ----------------
// C[M,N] = A[M,K](half,k-major) * B.  TRANSB: B[N,K].  else B[K,N].
// MASK: causal+scale epilogue on fp32 C; fully-masked tiles do NOTHING (no write).
// KLIMIT: truncate K at m0+128 (causal P exact zeros beyond).
// HOUT: write __half C (else fp32).
template<int TILE_N, bool TRANSB, bool MASK, bool KLIMIT, bool HOUT>
__global__ __launch_bounds__(256, 2)
void mm_h(const __half* __restrict__ A, const __half* __restrict__ Bm,
          void* __restrict__ Cv, int K, int lda, int ldb, int ldc,
          long long zsA, long long zsB, long long zsC, float scale)
{
    extern __shared__ __align__(16) char smc[];
    constexpr int STAGES = 3;
    constexpr int ASTG = 128 * 128;                    // bytes per A stage (128 rows x 64 halves)
    constexpr int SBH  = TILE_N + 8;                   // NN: halves per k-row
    constexpr int BSTG = TRANSB ? TILE_N * 128 : 64 * SBH * 2;
    constexpr int WN = TILE_N / 4;
    constexpr int NF = WN / 8;

    const int tid = threadIdx.x, lane = tid & 31, wid = tid >> 5;
    const int wm = wid & 1, wn = wid >> 1;
    const int m0 = blockIdx.y * 128;
    const int n0 = blockIdx.x * TILE_N;

    if (MASK && n0 > m0 + 127) return;   // never read by causal softmax

    A  += (long long)blockIdx.z * zsA;
    Bm += (long long)blockIdx.z * zsB;
    float*  Cf = (float*)Cv  + (long long)blockIdx.z * zsC;
    __half* Ch = (__half*)Cv + (long long)blockIdx.z * zsC;

    const uint32_t aB0 = smem_u32(smc);
    const uint32_t bB0 = aB0 + STAGES * ASTG;

    const int ktiles = KLIMIT ? (m0 + 128) / 64 : K / 64;

    float acc[4][NF][4];
    #pragma unroll
    for (int i = 0; i < 4; i++)
        #pragma unroll
        for (int j = 0; j < NF; j++)
            #pragma unroll
            for (int q = 0; q < 4; q++) acc[i][j][q] = 0.0f;

    auto load_stage = [&](int t, int s) {
        const int k0 = t * 64;
        #pragma unroll
        for (int j = 0; j < 4; j++) {
            int i = tid + j * 256, r = i >> 3, sg = i & 7;
            const __half* src = A + (long long)(m0 + r) * lda + k0 + sg * 8;
            CPA16(aB0 + s * ASTG + SWZ(r * 128 + sg * 16), src);
        }
        if (TRANSB) {
            #pragma unroll
            for (int j = 0; j < TILE_N * 8 / 256; j++) {
                int i = tid + j * 256, r = i >> 3, sg = i & 7;
                const __half* src = Bm + (long long)(n0 + r) * ldb + k0 + sg * 8;
                CPA16(bB0 + s * BSTG + SWZ(r * 128 + sg * 16), src);
            }
        } else {
            #pragma unroll
            for (int j = 0; j < 64 * (TILE_N / 8) / 256; j++) {
                int i = tid + j * 256, kk = i / (TILE_N / 8), sg = i % (TILE_N / 8);
                const __half* src = Bm + (long long)(k0 + kk) * ldb + n0 + sg * 8;
                CPA16(bB0 + s * BSTG + kk * (SBH * 2) + sg * 16, src);
            }
        }
    };

    // prologue: stages 0,1 (one commit group each)
    #pragma unroll
    for (int s = 0; s < STAGES - 1; s++) {
        if (s < ktiles) load_stage(s, s);
        CP_COMMIT();
    }

    for (int t = 0; t < ktiles; t++) {
        // drain group t (leaves <=1 outstanding), then ONE barrier for visibility
        CP_WAIT1();
        __syncthreads();

        // issue loads for stage t+2 into the stage computed at t-1 (safe: all
        // threads passed the barrier above after finishing compute(t-1))
        const int tn = t + STAGES - 1;
        if (tn < ktiles) load_stage(tn, tn % STAGES);
        CP_COMMIT();

        const uint32_t aS = aB0 + (t % STAGES) * ASTG;
        const uint32_t bS = bB0 + (t % STAGES) * BSTG;

        #pragma unroll
        for (int ks = 0; ks < 4; ks++) {
            uint32_t a[4][4];
            #pragma unroll
            for (int mf = 0; mf < 4; mf++) {
                int row = wm * 64 + mf * 16 + ((lane >> 3) & 1) * 8 + (lane & 7);
                uint32_t ad = aS + SWZ(row * 128 + ks * 32 + (lane >> 4) * 16);
                LDSM_X4(a[mf][0], a[mf][1], a[mf][2], a[mf][3], ad);
            }
            uint32_t b[NF][2];
            #pragma unroll
            for (int p = 0; p < NF / 2; p++) {
                uint32_t d0, d1, d2, d3;
                if (TRANSB) {
                    int row = wn * WN + p * 16 + (lane >> 4) * 8 + (lane & 7);
                    uint32_t bd = bS + SWZ(row * 128 + ks * 32 + ((lane >> 3) & 1) * 16);
                    LDSM_X4(d0, d1, d2, d3, bd);
                } else {
                    int kr  = ks * 16 + ((lane >> 3) & 1) * 8 + (lane & 7);
                    int col = wn * WN + p * 16 + (lane >> 4) * 8;
                    uint32_t bd = bS + kr * (SBH * 2) + col * 2;
                    LDSM_X4T(d0, d1, d2, d3, bd);
                }
                b[2 * p][0] = d0; b[2 * p][1] = d1;
                b[2 * p + 1][0] = d2; b[2 * p + 1][1] = d3;
            }
            #pragma unroll
            for (int mf = 0; mf < 4; mf++)
                #pragma unroll
                for (int nf = 0; nf < NF; nf++)
                    mma16(acc[mf][nf], a[mf], b[nf]);
        }
    }

    // ---- epilogue ----
    const float ni = __int_as_float(0xff800000);
    #pragma unroll
    for (int mf = 0; mf < 4; mf++) {
        const int r0 = m0 + wm * 64 + mf * 16 + (lane >> 2);
        const int r1 = r0 + 8;
        #pragma unroll
        for (int nf = 0; nf < NF; nf++) {
            const int c = n0 + wn * WN + nf * 8 + 2 * (lane & 3);
            float2 v0 = make_float2(acc[mf][nf][0], acc[mf][nf][1]);
            float2 v1 = make_float2(acc[mf][nf][2], acc[mf][nf][3]);
            if (MASK) {
                v0.x = (c     <= r0) ? v0.x * scale : ni;
                v0.y = (c + 1 <= r0) ? v0.y * scale : ni;
                v1.x = (c     <= r1) ? v1.x * scale : ni;
                v1.y = (c + 1 <= r1) ? v1.y * scale : ni;
            }
            if (HOUT) {
                *(__half2*)&Ch[(long long)r0 * ldc + c] = __floats2half2_rn(v0.x, v0.y);
                *(__half2*)&Ch[(long long)r1 * ldc + c] = __floats2half2_rn(v1.x, v1.y);
            } else {
                *(float2*)&Cf[(long long)r0 * ldc + c] = v0;
                *(float2*)&Cf[(long long)r1 * ldc + c] = v1;
            }
        }
    }
}

// ---------------- fp32 -> fp16 pre-pass ----------------
__global__ __launch_bounds__(256)
void f2h_kernel(const float4* __restrict__ src, __half2* __restrict__ dst, int n4)
{
    int i = blockIdx.x * 256 + threadIdx.x;
    if (i < n4) {
        float4 v = src[i];
        dst[2 * i]     = __floats2half2_rn(v.x, v.y);
        dst[2 * i + 1] = __floats2half2_rn(v.z, v.w);
    }
}

// ---------------- causal softmax: warp-per-row, all-register, shfl reductions ----
// Row r has valid logits in [0, r]; reads/writes [0, (r|127)+1) which matches
// exactly what the scores kernel wrote and what PV's KLIMIT window reads.
__global__ __launch_bounds__(256)
void softmax_kernel()
{
    const int gw   = blockIdx.x * 8 + (threadIdx.x >> 5);   // global warp = row
    const int lane = threadIdx.x & 31;
    const long long row = gw;
    const int r  = gw & (SEQ - 1);
    const int C4 = ((r | 127) + 1) >> 2;                    // float4 count, <= 512
    const float4* p4 = (const float4*)(g_P + row * SEQ);
    __half2* o2 = (__half2*)(g_Ph + row * SEQ);

    float4 v[16];
    float m = __int_as_float(0xff800000);
    #pragma unroll
    for (int j = 0; j < 16; j++) {
        int i = lane + j * 32;
        if (i < C4) {
            v[j] = p4[i];
            m = fmaxf(m, fmaxf(fmaxf(v[j].x, v[j].y), fmaxf(v[j].z, v[j].w)));
        }
    }
    #pragma unroll
    for (int off = 16; off > 0; off >>= 1)
        m = fmaxf(m, __shfl_xor_sync(0xffffffffu, m, off));

    float sum = 0.0f;
    #pragma unroll
    for (int j = 0; j < 16; j++) {
        int i = lane + j * 32;
        if (i < C4) {
            v[j].x = __expf(v[j].x - m); v[j].y = __expf(v[j].y - m);
            v[j].z = __expf(v[j].z - m); v[j].w = __expf(v[j].w - m);
            sum += (v[j].x + v[j].y) + (v[j].z + v[j].w);
        }
    }
    #pragma unroll
    for (int off = 16; off > 0; off >>= 1)
        sum += __shfl_xor_sync(0xffffffffu, sum, off);
    const float inv = 1.0f / sum;

    #pragma unroll
    for (int j = 0; j < 16; j++) {
        int i = lane + j * 32;
        if (i < C4) {
            o2[2 * i]     = __floats2half2_rn(v[j].x * inv, v[j].y * inv);
            o2[2 * i + 1] = __floats2half2_rn(v[j].z * inv, v[j].w * inv);
        }
    }
}

// ---------------- host ----------------
extern "C" void kernel_launch(void* const* d_in, const int* in_sizes, int n_in,
                              void* d_out, int out_size)
{
    const float* x  = (const float*)d_in[0];
    const float* Wq = (const float*)d_in[1];
    const float* Wk = (const float*)d_in[2];
    const float* Wv = (const float*)d_in[3];
    const float* Wo = (const float*)d_in[4];
    float* out = (float*)d_out;

    __half *Xh, *Wqh, *Wkh, *Wvh, *Woh, *Qh, *Kh, *Vh, *Ph, *Chx;
    float* P;
    cudaGetSymbolAddress((void**)&Xh,  g_Xh);
    cudaGetSymbolAddress((void**)&Wqh, g_Wqh);
    cudaGetSymbolAddress((void**)&Wkh, g_Wkh);
    cudaGetSymbolAddress((void**)&Wvh, g_Wvh);
    cudaGetSymbolAddress((void**)&Woh, g_Woh);
    cudaGetSymbolAddress((void**)&Qh,  g_Qh);
    cudaGetSymbolAddress((void**)&Kh,  g_Kh);
    cudaGetSymbolAddress((void**)&Vh,  g_Vh);
    cudaGetSymbolAddress((void**)&Ph,  g_Ph);
    cudaGetSymbolAddress((void**)&Chx, g_Ch);
    cudaGetSymbolAddress((void**)&P,   g_P);

    const int smNT128 = 3 * (16384 + 128 * 128);           // 98304  (96KB)
    const int smNN128 = 3 * (16384 + 64 * (128 + 8) * 2);  // 101376 (99KB)
    const int smNT64  = 3 * (16384 + 64 * 128);            // 73728
    cudaFuncSetAttribute(mm_h<128, true,  false, false, true >, cudaFuncAttributeMaxDynamicSharedMemorySize, smNT128);
    cudaFuncSetAttribute(mm_h<128, true,  true,  false, false>, cudaFuncAttributeMaxDynamicSharedMemorySize, smNT128);
    cudaFuncSetAttribute(mm_h<128, false, false, true,  true >, cudaFuncAttributeMaxDynamicSharedMemorySize, smNN128);
    cudaFuncSetAttribute(mm_h<64,  true,  false, false, false>, cudaFuncAttributeMaxDynamicSharedMemorySize, smNT64);

    // 0) round inputs to fp16
    f2h_kernel<<<(MTOT * DM / 4 + 255) / 256, 256>>>((const float4*)x,  (__half2*)Xh,  MTOT * DM / 4);
    f2h_kernel<<<(DM * DM / 4 + 255) / 256, 256>>>((const float4*)Wq, (__half2*)Wqh, DM * DM / 4);
    f2h_kernel<<<(DM * DM / 4 + 255) / 256, 256>>>((const float4*)Wk, (__half2*)Wkh, DM * DM / 4);
    f2h_kernel<<<(DM * DM / 4 + 255) / 256, 256>>>((const float4*)Wv, (__half2*)Wvh, DM * DM / 4);
    f2h_kernel<<<(DVAL * DM / 4 + 255) / 256, 256>>>((const float4*)Wo, (__half2*)Woh, DVAL * DM / 4);

    const dim3 blk(256);
    const float scale = 1.0f / 32.0f;   // 1/sqrt(1024)

    // 1) Q, K, V projections (NT, half out), 128x128 tiles, 2 CTA/SM
    mm_h<128, true, false, false, true><<<dim3(DM / 128, MTOT / 128, 1), blk, smNT128>>>(
        Xh, Wqh, Qh, DM, DM, DM, DM, 0, 0, 0, 1.0f);
    mm_h<128, true, false, false, true><<<dim3(DM / 128, MTOT / 128, 1), blk, smNT128>>>(
        Xh, Wkh, Kh, DM, DM, DM, DM, 0, 0, 0, 1.0f);
    mm_h<128, true, false, false, true><<<dim3(DM / 128, MTOT / 128, 1), blk, smNT128>>>(
        Xh, Wvh, Vh, DM, DM, DM, DM, 0, 0, 0, 1.0f);

    // 2) scores = mask(Q @ K^T) * scale  (NT + causal, fp32 out, lower tiles only)
    mm_h<128, true, true, false, false><<<dim3(SEQ / 128, SEQ / 128, BATCH), blk, smNT128>>>(
        Qh, Kh, P, DM, DM, DM, SEQ,
        (long long)SEQ * DM, (long long)SEQ * DM, (long long)SEQ * SEQ, scale);

    // 3) causal softmax: warp-per-row, fp32 scores -> fp16 probs
    softmax_kernel<<<MTOT / 8, 256>>>();

    // 4) ctx = P @ V  (NN + causal k-limit, half out)
    mm_h<128, false, false, true, true><<<dim3(DM / 128, SEQ / 128, BATCH), blk, smNN128>>>(
        Ph, Vh, Chx, SEQ, SEQ, DM, DM,
        (long long)SEQ * SEQ, (long long)SEQ * DM, (long long)SEQ * DM, 1.0f);

    // 5) out = ctx @ Wo^T  (NT, fp32 out)
    mm_h<64, true, false, false, false><<<dim3(DVAL / 64, MTOT / 128, 1), blk, smNT64>>>(
        Chx, Woh, out, DM, DM, DM, DVAL, 0, 0, 0, 1.0f);
}

// round 8
// speedup vs baseline: 7.2312x; 1.0426x over previous
#include <cuda_runtime.h>
#include <cuda_fp16.h>
#include <cstdint>
#include <math.h>

#define DM    1024
#define DM3   3072
#define BATCH 4
#define SEQ   2048
#define DVAL  64
#define MTOT  (BATCH*SEQ)   // 8192

// ---------------- scratch (device globals; no allocs allowed) ----------------
__device__ __half g_Xh   [(size_t)MTOT * DM];
__device__ __half g_Wh   [(size_t)DM3 * DM];      // Wq|Wk|Wv stacked rows
__device__ __half g_Woh  [(size_t)DVAL * DM];
__device__ __half g_QKVh [(size_t)MTOT * DM3];    // Q|K|V column slabs
__device__ __half g_Ph   [(size_t)BATCH * SEQ * SEQ];
__device__ __half g_Ch   [(size_t)MTOT * DM];
__device__ float  g_P    [(size_t)BATCH * SEQ * SEQ]; // fp32 scores (lower tiles only)

// ---------------- helpers ----------------
__device__ __forceinline__ uint32_t smem_u32(const void* p) {
    uint32_t a;
    asm("{ .reg .u64 t; cvta.to.shared.u64 t, %1; cvt.u32.u64 %0, t; }" : "=r"(a) : "l"(p));
    return a;
}
#define SWZ(o) ((o) ^ (((o) >> 3) & 0x70))

#define CPA16(dst, src) \
    asm volatile("cp.async.cg.shared.global [%0], [%1], 16;" :: "r"(dst), "l"(src) : "memory")
#define CP_COMMIT() asm volatile("cp.async.commit_group;" ::: "memory")
#define CP_WAIT1()  asm volatile("cp.async.wait_group 1;" ::: "memory")

#define LDSM_X4(d0, d1, d2, d3, a) \
    asm volatile("ldmatrix.sync.aligned.m8n8.x4.shared.b16 {%0,%1,%2,%3}, [%4];" \
        : "=r"(d0), "=r"(d1), "=r"(d2), "=r"(d3) : "r"(a))
#define LDSM_X4T(d0, d1, d2, d3, a) \
    asm volatile("ldmatrix.sync.aligned.m8n8.x4.trans.shared.b16 {%0,%1,%2,%3}, [%4];" \
        : "=r"(d0), "=r"(d1), "=r"(d2), "=r"(d3) : "r"(a))

__device__ __forceinline__ void mma16(float* c, const uint32_t* a, const uint32_t* b) {
    asm volatile(
        "mma.sync.aligned.m16n8k16.row.col.f32.f16.f16.f32 "
        "{%0,%1,%2,%3}, {%4,%5,%6,%7}, {%8,%9}, {%0,%1,%2,%3};"
        : "+f"(c[0]), "+f"(c[1]), "+f"(c[2]), "+f"(c[3])
        : "r"(a[0]), "r"(a[1]), "r"(a[2]), "r"(a[3]), "r"(b[0]), "r"(b[1]));
}

// ---------------- fp16 tensor-core GEMM ----------------
// C[M,N] = A[M,K](half,k-major) * B.  TRANSB: B[N,K].  else B[K,N].
// MASK: causal+scale epilogue on fp32 C; fully-masked tiles do NOTHING.
// KLIMIT: truncate K at m0+128.  HOUT: write __half C (else fp32).
template<int TILE_N, bool TRANSB, bool MASK, bool KLIMIT, bool HOUT>
__global__ __launch_bounds__(256, 2)
void mm_h(const __half* __restrict__ A, const __half* __restrict__ Bm,
          void* __restrict__ Cv, int K, int lda, int ldb, int ldc,
          long long zsA, long long zsB, long long zsC, float scale)
{
    extern __shared__ __align__(16) char smc[];
    constexpr int STAGES = 3;
    constexpr int ASTG = 128 * 128;
    constexpr int SBH  = TILE_N + 8;
    constexpr int BSTG = TRANSB ? TILE_N * 128 : 64 * SBH * 2;
    constexpr int WN = TILE_N / 4;
    constexpr int NF = WN / 8;

    const int tid = threadIdx.x, lane = tid & 31, wid = tid >> 5;
    const int wm = wid & 1, wn = wid >> 1;
    const int m0 = blockIdx.y * 128;
    const int n0 = blockIdx.x * TILE_N;

    if (MASK && n0 > m0 + 127) return;

    A  += (long long)blockIdx.z * zsA;
    Bm += (long long)blockIdx.z * zsB;
    float*  Cf = (float*)Cv  + (long long)blockIdx.z * zsC;
    __half* Ch = (__half*)Cv + (long long)blockIdx.z * zsC;

    const uint32_t aB0 = smem_u32(smc);
    const uint32_t bB0 = aB0 + STAGES * ASTG;

    const int ktiles = KLIMIT ? (m0 + 128) / 64 : K / 64;

    float acc[4][NF][4];
    #pragma unroll
    for (int i = 0; i < 4; i++)
        #pragma unroll
        for (int j = 0; j < NF; j++)
            #pragma unroll
            for (int q = 0; q < 4; q++) acc[i][j][q] = 0.0f;

    auto load_stage = [&](int t, int s) {
        const int k0 = t * 64;
        #pragma unroll
        for (int j = 0; j < 4; j++) {
            int i = tid + j * 256, r = i >> 3, sg = i & 7;
            const __half* src = A + (long long)(m0 + r) * lda + k0 + sg * 8;
            CPA16(aB0 + s * ASTG + SWZ(r * 128 + sg * 16), src);
        }
        if (TRANSB) {
            #pragma unroll
            for (int j = 0; j < TILE_N * 8 / 256; j++) {
                int i = tid + j * 256, r = i >> 3, sg = i & 7;
                const __half* src = Bm + (long long)(n0 + r) * ldb + k0 + sg * 8;
                CPA16(bB0 + s * BSTG + SWZ(r * 128 + sg * 16), src);
            }
        } else {
            #pragma unroll
            for (int j = 0; j < 64 * (TILE_N / 8) / 256; j++) {
                int i = tid + j * 256, kk = i / (TILE_N / 8), sg = i % (TILE_N / 8);
                const __half* src = Bm + (long long)(k0 + kk) * ldb + n0 + sg * 8;
                CPA16(bB0 + s * BSTG + kk * (SBH * 2) + sg * 16, src);
            }
        }
    };

    #pragma unroll
    for (int s = 0; s < STAGES - 1; s++) {
        if (s < ktiles) load_stage(s, s);
        CP_COMMIT();
    }

    uint32_t af[2][4][4];
    uint32_t bf[2][NF][2];

    for (int t = 0; t < ktiles; t++) {
        CP_WAIT1();
        __syncthreads();

        const int tn = t + STAGES - 1;
        if (tn < ktiles) load_stage(tn, tn % STAGES);
        CP_COMMIT();

        const uint32_t aS = aB0 + (t % STAGES) * ASTG;
        const uint32_t bS = bB0 + (t % STAGES) * BSTG;

        // fragment loader for one k-step into buffer pb
        auto load_frags = [&](int ks, int pb) {
            #pragma unroll
            for (int mf = 0; mf < 4; mf++) {
                int row = wm * 64 + mf * 16 + ((lane >> 3) & 1) * 8 + (lane & 7);
                uint32_t ad = aS + SWZ(row * 128 + ks * 32 + (lane >> 4) * 16);
                LDSM_X4(af[pb][mf][0], af[pb][mf][1], af[pb][mf][2], af[pb][mf][3], ad);
            }
            #pragma unroll
            for (int p = 0; p < NF / 2; p++) {
                uint32_t d0, d1, d2, d3;
                if (TRANSB) {
                    int row = wn * WN + p * 16 + (lane >> 4) * 8 + (lane & 7);
                    uint32_t bd = bS + SWZ(row * 128 + ks * 32 + ((lane >> 3) & 1) * 16);
                    LDSM_X4(d0, d1, d2, d3, bd);
                } else {
                    int kr  = ks * 16 + ((lane >> 3) & 1) * 8 + (lane & 7);
                    int col = wn * WN + p * 16 + (lane >> 4) * 8;
                    uint32_t bd = bS + kr * (SBH * 2) + col * 2;
                    LDSM_X4T(d0, d1, d2, d3, bd);
                }
                bf[pb][2 * p][0] = d0; bf[pb][2 * p][1] = d1;
                bf[pb][2 * p + 1][0] = d2; bf[pb][2 * p + 1][1] = d3;
            }
        };

        load_frags(0, 0);
        #pragma unroll
        for (int ks = 0; ks < 4; ks++) {
            const int cur = ks & 1;
            if (ks < 3) load_frags(ks + 1, cur ^ 1);   // hide LDSM under MMA
            #pragma unroll
            for (int mf = 0; mf < 4; mf++)
                #pragma unroll
                for (int nf = 0; nf < NF; nf++)
                    mma16(acc[mf][nf], af[cur][mf], bf[cur][nf]);
        }
    }

    // ---- epilogue ----
    const float ni = __int_as_float(0xff800000);
    #pragma unroll
    for (int mf = 0; mf < 4; mf++) {
        const int r0 = m0 + wm * 64 + mf * 16 + (lane >> 2);
        const int r1 = r0 + 8;
        #pragma unroll
        for (int nf = 0; nf < NF; nf++) {
            const int c = n0 + wn * WN + nf * 8 + 2 * (lane & 3);
            float2 v0 = make_float2(acc[mf][nf][0], acc[mf][nf][1]);
            float2 v1 = make_float2(acc[mf][nf][2], acc[mf][nf][3]);
            if (MASK) {
                v0.x = (c     <= r0) ? v0.x * scale : ni;
                v0.y = (c + 1 <= r0) ? v0.y * scale : ni;
                v1.x = (c     <= r1) ? v1.x * scale : ni;
                v1.y = (c + 1 <= r1) ? v1.y * scale : ni;
            }
            if (HOUT) {
                *(__half2*)&Ch[(long long)r0 * ldc + c] = __floats2half2_rn(v0.x, v0.y);
                *(__half2*)&Ch[(long long)r1 * ldc + c] = __floats2half2_rn(v1.x, v1.y);
            } else {
                *(float2*)&Cf[(long long)r0 * ldc + c] = v0;
                *(float2*)&Cf[(long long)r1 * ldc + c] = v1;
            }
        }
    }
}

// ---------------- fp32 -> fp16 pre-pass ----------------
__global__ __launch_bounds__(256)
void f2h_kernel(const float4* __restrict__ src, __half2* __restrict__ dst, int n4)
{
    int i = blockIdx.x * 256 + threadIdx.x;
    if (i < n4) {
        float4 v = src[i];
        dst[2 * i]     = __floats2half2_rn(v.x, v.y);
        dst[2 * i + 1] = __floats2half2_rn(v.z, v.w);
    }
}

// ---------------- causal softmax: warp-per-row, all-register ----------------
__global__ __launch_bounds__(256)
void softmax_kernel()
{
    const int gw   = blockIdx.x * 8 + (threadIdx.x >> 5);
    const int lane = threadIdx.x & 31;
    const long long row = gw;
    const int r  = gw & (SEQ - 1);
    const int C4 = ((r | 127) + 1) >> 2;
    const float4* p4 = (const float4*)(g_P + row * SEQ);
    __half2* o2 = (__half2*)(g_Ph + row * SEQ);

    float4 v[16];
    float m = __int_as_float(0xff800000);
    #pragma unroll
    for (int j = 0; j < 16; j++) {
        int i = lane + j * 32;
        if (i < C4) {
            v[j] = p4[i];
            m = fmaxf(m, fmaxf(fmaxf(v[j].x, v[j].y), fmaxf(v[j].z, v[j].w)));
        }
    }
    #pragma unroll
    for (int off = 16; off > 0; off >>= 1)
        m = fmaxf(m, __shfl_xor_sync(0xffffffffu, m, off));

    float sum = 0.0f;
    #pragma unroll
    for (int j = 0; j < 16; j++) {
        int i = lane + j * 32;
        if (i < C4) {
            v[j].x = __expf(v[j].x - m); v[j].y = __expf(v[j].y - m);
            v[j].z = __expf(v[j].z - m); v[j].w = __expf(v[j].w - m);
            sum += (v[j].x + v[j].y) + (v[j].z + v[j].w);
        }
    }
    #pragma unroll
    for (int off = 16; off > 0; off >>= 1)
        sum += __shfl_xor_sync(0xffffffffu, sum, off);
    const float inv = 1.0f / sum;

    #pragma unroll
    for (int j = 0; j < 16; j++) {
        int i = lane + j * 32;
        if (i < C4) {
            o2[2 * i]     = __floats2half2_rn(v[j].x * inv, v[j].y * inv);
            o2[2 * i + 1] = __floats2half2_rn(v[j].z * inv, v[j].w * inv);
        }
    }
}

// ---------------- host ----------------
extern "C" void kernel_launch(void* const* d_in, const int* in_sizes, int n_in,
                              void* d_out, int out_size)
{
    const float* x  = (const float*)d_in[0];
    const float* Wq = (const float*)d_in[1];
    const float* Wk = (const float*)d_in[2];
    const float* Wv = (const float*)d_in[3];
    const float* Wo = (const float*)d_in[4];
    float* out = (float*)d_out;

    __half *Xh, *Wh, *Woh, *QKVh, *Ph, *Chx;
    float* P;
    cudaGetSymbolAddress((void**)&Xh,   g_Xh);
    cudaGetSymbolAddress((void**)&Wh,   g_Wh);
    cudaGetSymbolAddress((void**)&Woh,  g_Woh);
    cudaGetSymbolAddress((void**)&QKVh, g_QKVh);
    cudaGetSymbolAddress((void**)&Ph,   g_Ph);
    cudaGetSymbolAddress((void**)&Chx,  g_Ch);
    cudaGetSymbolAddress((void**)&P,    g_P);

    const __half* Qh = QKVh;
    const __half* Kh = QKVh + DM;
    const __half* Vh = QKVh + 2 * DM;

    const int smNT128 = 3 * (16384 + 128 * 128);           // 96KB
    const int smNN128 = 3 * (16384 + 64 * (128 + 8) * 2);  // 99KB
    const int smNT64  = 3 * (16384 + 64 * 128);            // 72KB
    cudaFuncSetAttribute(mm_h<128, true,  false, false, true >, cudaFuncAttributeMaxDynamicSharedMemorySize, smNT128);
    cudaFuncSetAttribute(mm_h<128, true,  true,  false, false>, cudaFuncAttributeMaxDynamicSharedMemorySize, smNT128);
    cudaFuncSetAttribute(mm_h<128, false, false, true,  true >, cudaFuncAttributeMaxDynamicSharedMemorySize, smNN128);
    cudaFuncSetAttribute(mm_h<64,  true,  false, false, false>, cudaFuncAttributeMaxDynamicSharedMemorySize, smNT64);

    // 0) round inputs to fp16; stack Wq|Wk|Wv
    f2h_kernel<<<(MTOT * DM / 4 + 255) / 256, 256>>>((const float4*)x,  (__half2*)Xh, MTOT * DM / 4);
    f2h_kernel<<<(DM * DM / 4 + 255) / 256, 256>>>((const float4*)Wq, (__half2*)(Wh),              DM * DM / 4);
    f2h_kernel<<<(DM * DM / 4 + 255) / 256, 256>>>((const float4*)Wk, (__half2*)(Wh + DM * DM),     DM * DM / 4);
    f2h_kernel<<<(DM * DM / 4 + 255) / 256, 256>>>((const float4*)Wv, (__half2*)(Wh + 2 * DM * DM), DM * DM / 4);
    f2h_kernel<<<(DVAL * DM / 4 + 255) / 256, 256>>>((const float4*)Wo, (__half2*)Woh, DVAL * DM / 4);

    const dim3 blk(256);
    const float scale = 1.0f / 32.0f;   // 1/sqrt(1024)

    // 1) fused QKV projection: [8192,3072] = X @ [Wq|Wk|Wv]^T  (NT, half out)
    mm_h<128, true, false, false, true><<<dim3(DM3 / 128, MTOT / 128, 1), blk, smNT128>>>(
        Xh, Wh, QKVh, DM, DM, DM, DM3, 0, 0, 0, 1.0f);

    // 2) scores = mask(Q @ K^T) * scale  (NT + causal, fp32 out, lower tiles only)
    mm_h<128, true, true, false, false><<<dim3(SEQ / 128, SEQ / 128, BATCH), blk, smNT128>>>(
        Qh, Kh, P, DM, DM3, DM3, SEQ,
        (long long)SEQ * DM3, (long long)SEQ * DM3, (long long)SEQ * SEQ, scale);

    // 3) causal softmax: warp-per-row, fp32 scores -> fp16 probs
    softmax_kernel<<<MTOT / 8, 256>>>();

    // 4) ctx = P @ V  (NN + causal k-limit, half out)
    mm_h<128, false, false, true, true><<<dim3(DM / 128, SEQ / 128, BATCH), blk, smNN128>>>(
        Ph, Vh, Chx, SEQ, SEQ, DM3, DM,
        (long long)SEQ * SEQ, (long long)SEQ * DM3, (long long)SEQ * DM, 1.0f);

    // 5) out = ctx @ Wo^T  (NT, fp32 out)
    mm_h<64, true, false, false, false><<<dim3(DVAL / 64, MTOT / 128, 1), blk, smNT64>>>(
        Chx, Woh, out, DM, DM, DM, DVAL, 0, 0, 0, 1.0f);
}